// round 13
// baseline (speedup 1.0000x reference)
#include <cuda_runtime.h>
#include <cuda_bf16.h>
#include <math.h>
#include <stdint.h>

// ---------------- problem constants ----------------
#define Bsz   4
#define Lsz   2048
#define Dsz   2048
#define NHs   16
#define DHs   128
#define DHRs  64
#define DCs   1024
#define DTOT  (DHs + DHRs)     // 192
#define Msz   (Bsz * Lsz)      // 8192
#define BNHL  (Bsz * NHs * Lsz)  // 131072
#define NSMS  148

// ---------------- scratch ----------------
__device__ __align__(256) __nv_bfloat16 g_ckvqh[Msz * 2048];
__device__ __align__(256) __nv_bfloat16 g_ckvql[Msz * 2048];
__device__ __align__(256) __nv_bfloat16 g_aoh [Msz * Dsz];
__device__ __align__(256) __nv_bfloat16 g_aol [Msz * Dsz];
__device__ __align__(256) __nv_bfloat16 g_xh [Msz * Dsz];
__device__ __align__(256) __nv_bfloat16 g_xl [Msz * Dsz];
// attention operands (unnormalized; norm deferred to flash), hi/lo
__device__ __align__(256) __nv_bfloat16 g_Qch[BNHL * 128], g_Qcl[BNHL * 128];
__device__ __align__(256) __nv_bfloat16 g_Qrh[BNHL * 64],  g_Qrl[BNHL * 64];
__device__ __align__(256) __nv_bfloat16 g_Kch[BNHL * 128], g_Kcl[BNHL * 128];
__device__ __align__(256) __nv_bfloat16 g_krh[Msz * 64],   g_krl[Msz * 64];
__device__ __align__(256) __nv_bfloat16 g_Vh [BNHL * 128], g_Vl [BNHL * 128];
// norms
__device__ float g_ssqq[BNHL], g_ssqkc[BNHL], g_ssqkr[Msz];
__device__ float g_rq[BNHL], g_rk[BNHL];
__device__ float2 g_ropetab[Lsz * 32];
// stacked transposed weights [N x K] hi/lo
__device__ __align__(256) __nv_bfloat16 g_wdh[2176 * 2048], g_wdl[2176 * 2048];
__device__ __align__(256) __nv_bfloat16 g_wuh[7168 * 1024], g_wul[7168 * 1024];
__device__ __align__(256) __nv_bfloat16 g_woh[Dsz * Dsz],   g_wol[Dsz * Dsz];

#define LOG2_ROPE_BASE 13.287712379549449f

// ---------------- PTX helpers (baseline ISA only) ----------------
__device__ __forceinline__ uint32_t smem_u32(const void* p) {
    uint32_t a;
    asm("{ .reg .u64 t; cvta.to.shared.u64 t, %1; cvt.u32.u64 %0, t; }" : "=r"(a) : "l"(p));
    return a;
}
__device__ __forceinline__ void cpa16(uint32_t s, const void* g) {
    asm volatile("cp.async.cg.shared.global [%0], [%1], 16;" :: "r"(s), "l"(g) : "memory");
}
__device__ __forceinline__ void cp_commit() {
    asm volatile("cp.async.commit_group;" ::: "memory");
}
template <int N> __device__ __forceinline__ void cp_wait_group() {
    asm volatile("cp.async.wait_group %0;" :: "n"(N) : "memory");
}
__device__ __forceinline__ void ldm_x4(uint32_t* r, uint32_t addr) {
    asm volatile("ldmatrix.sync.aligned.m8n8.x4.shared.b16 {%0,%1,%2,%3}, [%4];"
                 : "=r"(r[0]), "=r"(r[1]), "=r"(r[2]), "=r"(r[3]) : "r"(addr));
}
__device__ __forceinline__ void ldm_x4_t(uint32_t* r, uint32_t addr) {
    asm volatile("ldmatrix.sync.aligned.m8n8.x4.trans.shared.b16 {%0,%1,%2,%3}, [%4];"
                 : "=r"(r[0]), "=r"(r[1]), "=r"(r[2]), "=r"(r[3]) : "r"(addr));
}
__device__ __forceinline__ void mma_bf16(float* c, const uint32_t* a, const uint32_t* b) {
    asm volatile(
        "mma.sync.aligned.m16n8k16.row.col.f32.bf16.bf16.f32 "
        "{%0,%1,%2,%3}, {%4,%5,%6,%7}, {%8,%9}, {%0,%1,%2,%3};"
        : "+f"(c[0]), "+f"(c[1]), "+f"(c[2]), "+f"(c[3])
        : "r"(a[0]), "r"(a[1]), "r"(a[2]), "r"(a[3]), "r"(b[0]), "r"(b[1]));
}
__device__ __forceinline__ uint32_t pack_bf162(float a, float b) {
    __nv_bfloat162 t;
    t.x = __float2bfloat16(a); t.y = __float2bfloat16(b);
    return *(uint32_t*)&t;
}
__device__ __forceinline__ void store_pair_hl(__nv_bfloat16* __restrict__ H,
                                              __nv_bfloat16* __restrict__ L,
                                              size_t o, float v0, float v1) {
    __nv_bfloat162 h2, l2;
    h2.x = __float2bfloat16(v0); h2.y = __float2bfloat16(v1);
    l2.x = __float2bfloat16(v0 - __bfloat162float(h2.x));
    l2.y = __float2bfloat16(v1 - __bfloat162float(h2.y));
    *(__nv_bfloat162*)&H[o] = h2;
    *(__nv_bfloat162*)&L[o] = l2;
}

// ---------------- fused prep: 8 weight tsplits + ropetab + ssq zero ----------------
#define PB_DKV 0
#define PB_DQ  2048
#define PB_KR  4096
#define PB_UK  4224
#define PB_UV  6272
#define PB_UQ  8320
#define PB_QR  10368
#define PB_WO  11392
#define PB_ROPE 15488
#define PB_ZERO (15488 + 256)
#define PB_TOTAL (PB_ZERO + BNHL / 256)

__global__ void __launch_bounds__(256)
prep_kernel(const float* __restrict__ Wdkv, const float* __restrict__ Wdq,
            const float* __restrict__ Wkr,  const float* __restrict__ Wuk,
            const float* __restrict__ Wuv,  const float* __restrict__ Wuq,
            const float* __restrict__ Wqr,  const float* __restrict__ Wo) {
    const int bid = blockIdx.x;
    const int tx = threadIdx.x & 31, ty = threadIdx.x >> 5;

    if (bid >= PB_ROPE) {
        int tid = ty * 32 + tx;
        if (bid < PB_ZERO) {
            int idx = (bid - PB_ROPE) * 256 + tid;
            int l = idx >> 5, i = idx & 31;
            float invf = exp2f(-(float)i * (LOG2_ROPE_BASE / 32.0f));
            float sn, cs;
            sincosf((float)l * invf, &sn, &cs);
            g_ropetab[idx] = make_float2(cs, sn);
        } else {
            int i = (bid - PB_ZERO) * 256 + tid;
            g_ssqq[i] = 0.f; g_ssqkc[i] = 0.f;
            if (i < Msz) g_ssqkr[i] = 0.f;
        }
        return;
    }

    const float* W; __nv_bfloat16 *Th, *Tl; int K, N, t;
    if (bid < PB_DQ)      { W = Wdkv; Th = g_wdh;                      Tl = g_wdl;                      K = 2048; N = 1024; t = bid; }
    else if (bid < PB_KR) { W = Wdq;  Th = g_wdh + (size_t)1024*2048;  Tl = g_wdl + (size_t)1024*2048;  K = 2048; N = 1024; t = bid - PB_DQ; }
    else if (bid < PB_UK) { W = Wkr;  Th = g_wdh + (size_t)2048*2048;  Tl = g_wdl + (size_t)2048*2048;  K = 2048; N = 64;   t = bid - PB_KR; }
    else if (bid < PB_UV) { W = Wuk;  Th = g_wuh;                      Tl = g_wul;                      K = 1024; N = 2048; t = bid - PB_UK; }
    else if (bid < PB_UQ) { W = Wuv;  Th = g_wuh + (size_t)2048*1024;  Tl = g_wul + (size_t)2048*1024;  K = 1024; N = 2048; t = bid - PB_UV; }
    else if (bid < PB_QR) { W = Wuq;  Th = g_wuh + (size_t)4096*1024;  Tl = g_wul + (size_t)4096*1024;  K = 1024; N = 2048; t = bid - PB_UQ; }
    else if (bid < PB_WO) { W = Wqr;  Th = g_wuh + (size_t)6144*1024;  Tl = g_wul + (size_t)6144*1024;  K = 1024; N = 1024; t = bid - PB_QR; }
    else                  { W = Wo;   Th = g_woh;                      Tl = g_wol;                      K = 2048; N = 2048; t = bid - PB_WO; }

    const int nbx = N >> 5;
    const int nb = (t % nbx) * 32;
    const int kb = (t / nbx) * 32;

    __shared__ float sh[32][33];
#pragma unroll
    for (int r = 0; r < 32; r += 8)
        sh[ty + r][tx] = W[(size_t)(kb + ty + r) * N + nb + tx];
    __syncthreads();
#pragma unroll
    for (int r = 0; r < 32; r += 8) {
        float x = sh[tx][ty + r];
        __nv_bfloat16 h = __float2bfloat16(x);
        float res = x - __bfloat162float(h);
        size_t o = (size_t)(nb + ty + r) * K + kb + tx;
        Th[o] = h;
        Tl[o] = __float2bfloat16(res);
    }
}

// ---------------- split x ----------------
__global__ void split_kernel(const float* __restrict__ src,
                             __nv_bfloat16* __restrict__ hi,
                             __nv_bfloat16* __restrict__ lo, int n) {
    int i0 = (blockIdx.x * 256 + threadIdx.x) * 8;
#pragma unroll
    for (int t = 0; t < 2; ++t) {
        int i = i0 + t * 4;
        if (i < n) {
            float4 v = *(const float4*)&src[i];
            __nv_bfloat162 h0, h1, l0, l1;
            h0.x = __float2bfloat16(v.x); h0.y = __float2bfloat16(v.y);
            h1.x = __float2bfloat16(v.z); h1.y = __float2bfloat16(v.w);
            l0.x = __float2bfloat16(v.x - __bfloat162float(h0.x));
            l0.y = __float2bfloat16(v.y - __bfloat162float(h0.y));
            l1.x = __float2bfloat16(v.z - __bfloat162float(h1.x));
            l1.y = __float2bfloat16(v.w - __bfloat162float(h1.y));
            *(__nv_bfloat162*)&hi[i]     = h0;
            *(__nv_bfloat162*)&hi[i + 2] = h1;
            *(__nv_bfloat162*)&lo[i]     = l0;
            *(__nv_bfloat162*)&lo[i + 2] = l1;
        }
    }
}

__global__ void norm_kernel(const float* __restrict__ s_qk_ptr) {
    int i = blockIdx.x * 256 + threadIdx.x;
    if (i >= BNHL) return;
    float s = *s_qk_ptr;
    int b = i >> 15, l = i & 2047;
    int bl = (b << 11) + l;
    g_rq[i] = s * rsqrtf(fmaxf(g_ssqq[i], 1e-24f));
    g_rk[i] = rsqrtf(fmaxf(g_ssqkc[i] + g_ssqkr[bl], 1e-24f));
}

// ---------------- persistent mma.sync bf16 split-3 GEMM (4-stage ring across tiles) ----------------
// CTA 256x128x32, 8 warps (4m x 2n), warp tile 64x64. Grid = 148 persistent CTAs.
// epmode: 0 = fp32 Cf; 1 = down-proj (ckvq bf16 + rope-K); 2 = up-proj (Kc/V/Qc/rope-Q)
#define MMS_A_H 0
#define MMS_A_L 16384
#define MMS_B_H 32768
#define MMS_B_L 40960
#define MMS_STAGE 49152
#define MM_SMEM (4 * MMS_STAGE)   // 196608

__device__ __forceinline__ void mm_load_chunk(
    uint32_t sbase, int p, int nksh, int nxt, int bid,
    const __nv_bfloat16* __restrict__ Ahg, const __nv_bfloat16* __restrict__ Alg,
    const __nv_bfloat16* __restrict__ Ahg2, const __nv_bfloat16* __restrict__ Alg2,
    int aswitch, int Astride,
    const __nv_bfloat16* __restrict__ Bhg, const __nv_bfloat16* __restrict__ Blg,
    int Kd, int tid)
{
    int t = bid + (p >> nksh) * NSMS;
    int m0 = (t / nxt) * 256;
    int n0 = (t % nxt) * 128;
    int k0 = (p & ((1 << nksh) - 1)) << 5;
    const __nv_bfloat16* Ah = (n0 >= aswitch) ? Ahg2 : Ahg;
    const __nv_bfloat16* Al = (n0 >= aswitch) ? Alg2 : Alg;
#pragma unroll
    for (int tt = 0; tt < 4; ++tt) {
        int idx = tid + tt * 256;
        int row = idx >> 2, c = idx & 3;
        uint32_t so = (uint32_t)(row * 64 + ((c ^ (row & 3)) << 4));
        size_t g = (size_t)(m0 + row) * Astride + k0 + c * 8;
        cpa16(sbase + MMS_A_H + so, Ah + g);
        cpa16(sbase + MMS_A_L + so, Al + g);
    }
#pragma unroll
    for (int tt = 0; tt < 2; ++tt) {
        int idx = tid + tt * 256;
        int row = idx >> 2, c = idx & 3;
        uint32_t so = (uint32_t)(row * 64 + ((c ^ (row & 3)) << 4));
        size_t g = (size_t)(n0 + row) * Kd + k0 + c * 8;
        cpa16(sbase + MMS_B_H + so, Bhg + g);
        cpa16(sbase + MMS_B_L + so, Blg + g);
    }
}

__global__ void __launch_bounds__(256, 1)
mm_mma_kernel(const __nv_bfloat16* __restrict__ Ahg, const __nv_bfloat16* __restrict__ Alg,
              const __nv_bfloat16* __restrict__ Ahg2, const __nv_bfloat16* __restrict__ Alg2,
              int aswitch, int Astride,
              const __nv_bfloat16* __restrict__ Bhg, const __nv_bfloat16* __restrict__ Blg,
              float* __restrict__ Cf,
              int Md, int Nd, int Kd, int epmode) {
    extern __shared__ __align__(1024) char smem[];
    const uint32_t sb = smem_u32(smem);
    const int tid = threadIdx.x, wid = tid >> 5, lane = tid & 31;
    const int bid = blockIdx.x;
    const int mw = (wid & 3) * 64;
    const int nw = (wid >> 2) * 64;

    const int nxt = Nd >> 7;
    const int ntiles = nxt * (Md >> 8);
    const int nk = Kd >> 5;
    const int nksh = (Kd == 2048) ? 6 : 5;
    const int nkm = nk - 1;
    const int mytiles = (ntiles - bid + NSMS - 1) / NSMS;
    if (mytiles <= 0) return;
    const int nchunks = mytiles << nksh;

    float acc[4][8][4];
#pragma unroll
    for (int i = 0; i < 4; ++i)
#pragma unroll
        for (int j = 0; j < 8; ++j)
#pragma unroll
            for (int q = 0; q < 4; ++q) acc[i][j][q] = 0.f;

#pragma unroll
    for (int s = 0; s < 3; ++s) {
        if (s < nchunks)
            mm_load_chunk(sb + s * MMS_STAGE, s, nksh, nxt, bid,
                          Ahg, Alg, Ahg2, Alg2, aswitch, Astride, Bhg, Blg, Kd, tid);
        cp_commit();
    }

    const int jA = lane >> 3, rA = lane & 7;

    int sidx = 0;
    for (int p = 0; p < nchunks; ++p) {
        cp_wait_group<2>();
        __syncthreads();

        if (p + 3 < nchunks) {
            int ps = sidx + 3; if (ps >= 4) ps -= 4;
            mm_load_chunk(sb + ps * MMS_STAGE, p + 3, nksh, nxt, bid,
                          Ahg, Alg, Ahg2, Alg2, aswitch, Astride, Bhg, Blg, Kd, tid);
        }
        cp_commit();

        const uint32_t stg = sb + sidx * MMS_STAGE;

#pragma unroll
        for (int ks = 0; ks < 2; ++ks) {
            uint32_t ah[4][4], al[4][4];
#pragma unroll
            for (int i = 0; i < 4; ++i) {
                int m = mw + i * 16 + ((jA & 1) << 3) + rA;
                int c = (ks << 1) + (jA >> 1);
                uint32_t off = (uint32_t)(m * 64 + ((c ^ (m & 3)) << 4));
                ldm_x4(ah[i], stg + MMS_A_H + off);
                ldm_x4(al[i], stg + MMS_A_L + off);
            }
            uint32_t bh[8][2], bl[8][2];
#pragma unroll
            for (int pp = 0; pp < 4; ++pp) {
                int n = nw + pp * 16 + ((jA >> 1) << 3) + rA;
                int c = (ks << 1) + (jA & 1);
                uint32_t off = (uint32_t)(n * 64 + ((c ^ (n & 3)) << 4));
                uint32_t tmp[4];
                ldm_x4(tmp, stg + MMS_B_H + off);
                bh[2 * pp][0] = tmp[0]; bh[2 * pp][1] = tmp[1];
                bh[2 * pp + 1][0] = tmp[2]; bh[2 * pp + 1][1] = tmp[3];
                ldm_x4(tmp, stg + MMS_B_L + off);
                bl[2 * pp][0] = tmp[0]; bl[2 * pp][1] = tmp[1];
                bl[2 * pp + 1][0] = tmp[2]; bl[2 * pp + 1][1] = tmp[3];
            }
#pragma unroll
            for (int i = 0; i < 4; ++i)
#pragma unroll
                for (int j = 0; j < 8; ++j) {
                    mma_bf16(acc[i][j], ah[i], bh[j]);
                    mma_bf16(acc[i][j], al[i], bh[j]);
                    mma_bf16(acc[i][j], ah[i], bl[j]);
                }
        }
        if (++sidx == 4) sidx = 0;

        if ((p & nkm) != nkm) continue;

        // ================= tile epilogue (overlaps next tile's in-flight loads) =================
        {
            int t = bid + (p >> nksh) * NSMS;
            int m0 = (t / nxt) * 256;
            int n0 = (t % nxt) * 128;

            if (epmode == 0) {
#pragma unroll
                for (int i = 0; i < 4; ++i) {
                    int row = m0 + mw + i * 16 + (lane >> 2);
#pragma unroll
                    for (int j = 0; j < 8; ++j) {
                        int col = n0 + nw + j * 8 + ((lane & 3) << 1);
                        *(float2*)&Cf[(size_t)row * Nd + col]       = make_float2(acc[i][j][0], acc[i][j][1]);
                        *(float2*)&Cf[(size_t)(row + 8) * Nd + col] = make_float2(acc[i][j][2], acc[i][j][3]);
                    }
                }
            } else if (epmode == 1) {
                if (n0 < 2048) {
#pragma unroll
                    for (int i = 0; i < 4; ++i) {
                        int row = m0 + mw + i * 16 + (lane >> 2);
#pragma unroll
                        for (int j = 0; j < 8; ++j) {
                            int col = n0 + nw + j * 8 + ((lane & 3) << 1);
                            store_pair_hl(g_ckvqh, g_ckvql, (size_t)row * 2048 + col, acc[i][j][0], acc[i][j][1]);
                            store_pair_hl(g_ckvqh, g_ckvql, (size_t)(row + 8) * 2048 + col, acc[i][j][2], acc[i][j][3]);
                        }
                    }
                } else if (nw == 0) {
                    // rope-K: cols 2048..2111 -> dr 0..63
#pragma unroll
                    for (int i = 0; i < 4; ++i) {
                        int rbase = m0 + mw + i * 16 + (lane >> 2);
#pragma unroll
                        for (int hh = 0; hh < 2; ++hh) {
                            int rr = rbase + hh * 8;
                            int l = rr & 2047;
                            float ssq = 0.f;
                            float o0[8], o1[8];
#pragma unroll
                            for (int j = 0; j < 8; ++j) {
                                float x1a = acc[i][j][2 * hh], x1b = acc[i][j][2 * hh + 1];
                                int jp = j ^ 4;
                                float sgn = (j < 4) ? -1.f : 1.f;
                                float x2a = acc[i][jp][2 * hh], x2b = acc[i][jp][2 * hh + 1];
                                int i0 = ((j & 3) << 3) + ((lane & 3) << 1);
                                float2 cs0 = g_ropetab[(l << 5) + i0];
                                float2 cs1 = g_ropetab[(l << 5) + i0 + 1];
                                o0[j] = x1a * cs0.x + sgn * x2a * cs0.y;
                                o1[j] = x1b * cs1.x + sgn * x2b * cs1.y;
                                ssq += x1a * x1a + x1b * x1b;
                            }
                            ssq += __shfl_xor_sync(0xffffffffu, ssq, 1);
                            ssq += __shfl_xor_sync(0xffffffffu, ssq, 2);
                            if ((lane & 3) == 0) atomicAdd(&g_ssqkr[rr], ssq);
#pragma unroll
                            for (int j = 0; j < 8; ++j) {
                                int dr = (j << 3) + ((lane & 3) << 1);
                                store_pair_hl(g_krh, g_krl, (size_t)rr * 64 + dr, o0[j], o1[j]);
                            }
                        }
                    }
                }
            } else {
                int region = n0 >> 11;        // 0 UK, 1 UV, 2 UQ, 3 QR
                if (region < 3) {
                    int cbase = (n0 + nw) & 2047;
                    int h = cbase >> 7, dbase = cbase & 127;
#pragma unroll
                    for (int i = 0; i < 4; ++i) {
                        int rbase = m0 + mw + i * 16 + (lane >> 2);
#pragma unroll
                        for (int hh = 0; hh < 2; ++hh) {
                            int rr = rbase + hh * 8;
                            int bb = rr >> 11, l = rr & 2047;
                            size_t hidx = (size_t)(bb * NHs + h) * 2048 + l;
                            size_t hb = hidx * 128 + dbase;
                            float ssq = 0.f;
#pragma unroll
                            for (int j = 0; j < 8; ++j) {
                                float v0 = acc[i][j][2 * hh], v1 = acc[i][j][2 * hh + 1];
                                int d = (j << 3) + ((lane & 3) << 1);
                                if (region == 0)      store_pair_hl(g_Kch, g_Kcl, hb + d, v0, v1);
                                else if (region == 1) store_pair_hl(g_Vh,  g_Vl,  hb + d, v0, v1);
                                else                  store_pair_hl(g_Qch, g_Qcl, hb + d, v0, v1);
                                ssq += v0 * v0 + v1 * v1;
                            }
                            if (region != 1) {
                                ssq += __shfl_xor_sync(0xffffffffu, ssq, 1);
                                ssq += __shfl_xor_sync(0xffffffffu, ssq, 2);
                                if ((lane & 3) == 0)
                                    atomicAdd(region == 0 ? &g_ssqkc[hidx] : &g_ssqq[hidx], ssq);
                            }
                        }
                    }
                } else {
                    int local0 = (n0 - 6144) + nw;
                    int h = local0 >> 6;
#pragma unroll
                    for (int i = 0; i < 4; ++i) {
                        int rbase = m0 + mw + i * 16 + (lane >> 2);
#pragma unroll
                        for (int hh = 0; hh < 2; ++hh) {
                            int rr = rbase + hh * 8;
                            int bb = rr >> 11, l = rr & 2047;
                            size_t hidx = (size_t)(bb * NHs + h) * 2048 + l;
                            float ssq = 0.f;
                            float o0[8], o1[8];
#pragma unroll
                            for (int j = 0; j < 8; ++j) {
                                float x1a = acc[i][j][2 * hh], x1b = acc[i][j][2 * hh + 1];
                                int jp = j ^ 4;
                                float sgn = (j < 4) ? -1.f : 1.f;
                                float x2a = acc[i][jp][2 * hh], x2b = acc[i][jp][2 * hh + 1];
                                int i0 = ((j & 3) << 3) + ((lane & 3) << 1);
                                float2 cs0 = g_ropetab[(l << 5) + i0];
                                float2 cs1 = g_ropetab[(l << 5) + i0 + 1];
                                o0[j] = x1a * cs0.x + sgn * x2a * cs0.y;
                                o1[j] = x1b * cs1.x + sgn * x2b * cs1.y;
                                ssq += x1a * x1a + x1b * x1b;
                            }
                            ssq += __shfl_xor_sync(0xffffffffu, ssq, 1);
                            ssq += __shfl_xor_sync(0xffffffffu, ssq, 2);
                            if ((lane & 3) == 0) atomicAdd(&g_ssqq[hidx], ssq);
#pragma unroll
                            for (int j = 0; j < 8; ++j) {
                                int dr = (j << 3) + ((lane & 3) << 1);
                                store_pair_hl(g_Qrh, g_Qrl, hidx * 64 + dr, o0[j], o1[j]);
                            }
                        }
                    }
                }
            }
            // reset accumulators for next tile
#pragma unroll
            for (int i = 0; i < 4; ++i)
#pragma unroll
                for (int j = 0; j < 8; ++j)
#pragma unroll
                    for (int q = 0; q < 4; ++q) acc[i][j][q] = 0.f;
        }
    }
}

// ---------------- tensor-core causal flash attention (split-3 bf16, register P, deferred norm) ----------------
#define FQ 128
#define FK 64
#define SQH 0
#define SQL (SQH + FQ*384)
#define SKH (SQL + FQ*384)
#define SKL (SKH + FK*384)
#define SV0H (SKL + FK*384)
#define SV0L (SV0H + FK*256)
#define SV1H (SV0L + FK*256)
#define SV1L (SV1H + FK*256)
#define FLASH_SMEM (SV1L + FK*256)   // 212992

__device__ __forceinline__ void fl_load_q(uint32_t sb, int b, int h, int q0, int tid) {
    size_t cb = (size_t)(b * NHs + h) * Lsz + q0;
    for (int idx = tid; idx < FQ * 24; idx += 256) {
        int r = idx / 24, c = idx % 24;
        uint32_t so = (uint32_t)(r * 384 + ((c ^ (r & 7)) << 4));
        if (c < 16) {
            size_t g = (cb + r) * 128 + c * 8;
            cpa16(sb + SQH + so, g_Qch + g);
            cpa16(sb + SQL + so, g_Qcl + g);
        } else {
            size_t g = (cb + r) * 64 + (c - 16) * 8;
            cpa16(sb + SQH + so, g_Qrh + g);
            cpa16(sb + SQL + so, g_Qrl + g);
        }
    }
}
__device__ __forceinline__ void fl_load_k(uint32_t sb, int b, int h, int k0, int tid) {
    size_t cb = (size_t)(b * NHs + h) * Lsz + k0;
    size_t rb = (size_t)b * Lsz + k0;
    for (int idx = tid; idx < FK * 24; idx += 256) {
        int r = idx / 24, c = idx % 24;
        uint32_t so = (uint32_t)(r * 384 + ((c ^ (r & 7)) << 4));
        if (c < 16) {
            size_t g = (cb + r) * 128 + c * 8;
            cpa16(sb + SKH + so, g_Kch + g);
            cpa16(sb + SKL + so, g_Kcl + g);
        } else {
            size_t g = (rb + r) * 64 + (c - 16) * 8;
            cpa16(sb + SKH + so, g_krh + g);
            cpa16(sb + SKL + so, g_krl + g);
        }
    }
}
__device__ __forceinline__ void fl_load_v(uint32_t sb, uint32_t vH, uint32_t vL,
                                          int b, int h, int k0, int tid) {
    size_t gb = ((size_t)(b * NHs + h) * Lsz + k0) * DHs;
    for (int idx = tid; idx < FK * 16; idx += 256) {
        int r = idx >> 4, c = idx & 15;
        uint32_t so = (uint32_t)(r * 256 + ((c ^ (r & 7)) << 4));
        size_t g = gb + (size_t)r * DHs + c * 8;
        cpa16(sb + vH + so, g_Vh + g);
        cpa16(sb + vL + so, g_Vl + g);
    }
}

__global__ void __launch_bounds__(256, 1)
flashmma_kernel() {
    extern __shared__ __align__(1024) char sm[];
    const uint32_t sb = smem_u32(sm);
    const int tid = threadIdx.x, w = tid >> 5, lane = tid & 31;
    const int qt = (int)(gridDim.x - 1u - blockIdx.x);
    const int h = blockIdx.y, b = blockIdx.z;
    const int q0 = qt * FQ;
    const int mw = w * 16;
    const int jA = lane >> 3, rA = lane & 7;

    fl_load_q(sb, b, h, q0, tid);
    cp_commit();
    fl_load_k(sb, b, h, 0, tid);
    fl_load_v(sb, SV0H, SV0L, b, h, 0, tid);
    cp_commit();

    float oacc[16][4];
#pragma unroll
    for (int j = 0; j < 16; ++j)
#pragma unroll
        for (int q = 0; q < 4; ++q) oacc[j][q] = 0.f;
    float m0 = -1e30f, m1 = -1e30f, l0 = 0.f, l1 = 0.f;

    const int nkt = 2 * qt + 2;
    const int r0loc = mw + (lane >> 2);
    const int gr0 = q0 + r0loc;

    const float* rqb = g_rq + (size_t)(b * NHs + h) * Lsz;
    const float* rkb = g_rk + (size_t)(b * NHs + h) * Lsz;
    const float rq0 = rqb[gr0], rq1 = rqb[gr0 + 8];

    for (int kt = 0; kt < nkt; ++kt) {
        const int k0 = kt * FK;
        float2 rkv[8];
#pragma unroll
        for (int j = 0; j < 8; ++j)
            rkv[j] = *(const float2*)&rkb[k0 + j * 8 + ((lane & 3) << 1)];

        cp_wait_group<0>();
        __syncthreads();

        // V(kt+1) load issued EARLY (double-buffered; buffer (kt+1)&1 was consumed in iter kt-1)
        if (kt + 1 < nkt) {
            uint32_t vH = ((kt + 1) & 1) ? SV1H : SV0H;
            uint32_t vL = ((kt + 1) & 1) ? SV1L : SV0L;
            fl_load_v(sb, vH, vL, b, h, (kt + 1) * FK, tid);
        }
        cp_commit();

        // ---- S = Q K^T (split-3, unnormalized) ----
        float sacc[8][4];
#pragma unroll
        for (int j = 0; j < 8; ++j)
#pragma unroll
            for (int q = 0; q < 4; ++q) sacc[j][q] = 0.f;

#pragma unroll
        for (int ks = 0; ks < 12; ++ks) {
            int arow = mw + ((jA & 1) << 3) + rA;
            int achk = ks * 2 + (jA >> 1);
            uint32_t aoff = (uint32_t)(arow * 384 + ((achk ^ (arow & 7)) << 4));
            uint32_t ah[4], al[4];
            ldm_x4(ah, sb + SQH + aoff);
            ldm_x4(al, sb + SQL + aoff);
            uint32_t bh[8][2], bl[8][2];
#pragma unroll
            for (int p = 0; p < 4; ++p) {
                int brow = p * 16 + ((jA >> 1) << 3) + rA;
                int bchk = ks * 2 + (jA & 1);
                uint32_t boff = (uint32_t)(brow * 384 + ((bchk ^ (brow & 7)) << 4));
                uint32_t tmp[4];
                ldm_x4(tmp, sb + SKH + boff);
                bh[2 * p][0] = tmp[0]; bh[2 * p][1] = tmp[1];
                bh[2 * p + 1][0] = tmp[2]; bh[2 * p + 1][1] = tmp[3];
                ldm_x4(tmp, sb + SKL + boff);
                bl[2 * p][0] = tmp[0]; bl[2 * p][1] = tmp[1];
                bl[2 * p + 1][0] = tmp[2]; bl[2 * p + 1][1] = tmp[3];
            }
#pragma unroll
            for (int j = 0; j < 8; ++j) {
                mma_bf16(sacc[j], ah, bh[j]);
                mma_bf16(sacc[j], al, bh[j]);
                mma_bf16(sacc[j], ah, bl[j]);
            }
        }

        // ---- deferred normalization: S *= rq_row * rk_col ----
#pragma unroll
        for (int j = 0; j < 8; ++j) {
            sacc[j][0] *= rq0 * rkv[j].x;
            sacc[j][1] *= rq0 * rkv[j].y;
            sacc[j][2] *= rq1 * rkv[j].x;
            sacc[j][3] *= rq1 * rkv[j].y;
        }

        // ---- causal mask (last two k-tiles only) ----
        if (kt >= 2 * qt) {
#pragma unroll
            for (int j = 0; j < 8; ++j) {
                int col = k0 + j * 8 + ((lane & 3) << 1);
                if (col > gr0)     sacc[j][0] = -1e30f;
                if (col + 1 > gr0) sacc[j][1] = -1e30f;
                if (col > gr0 + 8)     sacc[j][2] = -1e30f;
                if (col + 1 > gr0 + 8) sacc[j][3] = -1e30f;
            }
        }

        // ---- online softmax (register P, hi/lo fragments) ----
        float mx0 = -1e30f, mx1 = -1e30f;
#pragma unroll
        for (int j = 0; j < 8; ++j) {
            mx0 = fmaxf(mx0, fmaxf(sacc[j][0], sacc[j][1]));
            mx1 = fmaxf(mx1, fmaxf(sacc[j][2], sacc[j][3]));
        }
#pragma unroll
        for (int o = 1; o <= 2; o <<= 1) {
            mx0 = fmaxf(mx0, __shfl_xor_sync(0xffffffffu, mx0, o));
            mx1 = fmaxf(mx1, __shfl_xor_sync(0xffffffffu, mx1, o));
        }
        float mn0 = fmaxf(m0, mx0), mn1 = fmaxf(m1, mx1);
        float sc0 = __expf(m0 - mn0), sc1 = __expf(m1 - mn1);
        m0 = mn0; m1 = mn1;

        uint32_t pfh[4][4], pfl[4][4];
        float rs0 = 0.f, rs1 = 0.f;
#pragma unroll
        for (int j = 0; j < 8; ++j) {
            float p0 = __expf(sacc[j][0] - mn0);
            float p1 = __expf(sacc[j][1] - mn0);
            float p2 = __expf(sacc[j][2] - mn1);
            float p3 = __expf(sacc[j][3] - mn1);
            rs0 += p0 + p1; rs1 += p2 + p3;
            __nv_bfloat162 h01, h23;
            h01.x = __float2bfloat16(p0); h01.y = __float2bfloat16(p1);
            h23.x = __float2bfloat16(p2); h23.y = __float2bfloat16(p3);
            int t = j >> 1, s = (j & 1) * 2;
            pfh[t][s + 0] = *(uint32_t*)&h01;
            pfh[t][s + 1] = *(uint32_t*)&h23;
            pfl[t][s + 0] = pack_bf162(p0 - __bfloat162float(h01.x),
                                       p1 - __bfloat162float(h01.y));
            pfl[t][s + 1] = pack_bf162(p2 - __bfloat162float(h23.x),
                                       p3 - __bfloat162float(h23.y));
        }
#pragma unroll
        for (int o = 1; o <= 2; o <<= 1) {
            rs0 += __shfl_xor_sync(0xffffffffu, rs0, o);
            rs1 += __shfl_xor_sync(0xffffffffu, rs1, o);
        }
        l0 = l0 * sc0 + rs0;
        l1 = l1 * sc1 + rs1;
#pragma unroll
        for (int j = 0; j < 16; ++j) {
            oacc[j][0] *= sc0; oacc[j][1] *= sc0;
            oacc[j][2] *= sc1; oacc[j][3] *= sc1;
        }

        __syncthreads();                // all warps done reading K(kt)

        if (kt + 1 < nkt)
            fl_load_k(sb, b, h, (kt + 1) * FK, tid);
        cp_commit();

        // ---- O += P V (split-3), V from buffer kt&1, P from registers ----
        const uint32_t vH = (kt & 1) ? SV1H : SV0H;
        const uint32_t vL = (kt & 1) ? SV1L : SV0L;
#pragma unroll
        for (int ks = 0; ks < 4; ++ks) {
            int key = ks * 16 + (lane & 15);
#pragma unroll
            for (int p = 0; p < 8; ++p) {
                int dch = p * 2 + (lane >> 4);
                uint32_t voff = (uint32_t)(key * 256 + ((dch ^ (key & 7)) << 4));
                uint32_t th[4], tl[4];
                ldm_x4_t(th, sb + vH + voff);
                ldm_x4_t(tl, sb + vL + voff);
                mma_bf16(oacc[2 * p], pfh[ks], th);
                mma_bf16(oacc[2 * p], pfl[ks], th);
                mma_bf16(oacc[2 * p], pfh[ks], tl);
                mma_bf16(oacc[2 * p + 1], pfh[ks], th + 2);
                mma_bf16(oacc[2 * p + 1], pfl[ks], th + 2);
                mma_bf16(oacc[2 * p + 1], pfh[ks], tl + 2);
            }
        }
    }

    // ---- epilogue: normalize, split, write (B,L,D) bf16 hi/lo ----
    float inv0 = 1.0f / l0, inv1 = 1.0f / l1;
    size_t ob0 = ((size_t)(b * Lsz + gr0)) * Dsz + h * DHs;
    size_t ob1 = ((size_t)(b * Lsz + gr0 + 8)) * Dsz + h * DHs;
#pragma unroll
    for (int j = 0; j < 16; ++j) {
        int d = j * 8 + ((lane & 3) << 1);
        store_pair_hl(g_aoh, g_aol, ob0 + d, oacc[j][0] * inv0, oacc[j][1] * inv0);
        store_pair_hl(g_aoh, g_aol, ob1 + d, oacc[j][2] * inv1, oacc[j][3] * inv1);
    }
}

// ---------------- launcher ----------------
extern "C" void kernel_launch(void* const* d_in, const int* in_sizes, int n_in,
                              void* d_out, int out_size) {
    const float* x     = (const float*)d_in[0];
    const float* W_DKV = (const float*)d_in[1];
    const float* W_UK  = (const float*)d_in[2];
    const float* W_UV  = (const float*)d_in[3];
    const float* W_DQ  = (const float*)d_in[4];
    const float* W_UQ  = (const float*)d_in[5];
    const float* W_QR  = (const float*)d_in[6];
    const float* W_KR  = (const float*)d_in[7];
    const float* W_O   = (const float*)d_in[8];
    const float* s_qk  = (const float*)d_in[9];
    float* out = (float*)d_out;

    __nv_bfloat16 *xh, *xl, *cvh, *cvl, *aoh, *aol;
    __nv_bfloat16 *wdh, *wdl, *wuh, *wul, *woh, *wol;
    cudaGetSymbolAddress((void**)&xh, g_xh);     cudaGetSymbolAddress((void**)&xl, g_xl);
    cudaGetSymbolAddress((void**)&cvh, g_ckvqh); cudaGetSymbolAddress((void**)&cvl, g_ckvql);
    cudaGetSymbolAddress((void**)&aoh, g_aoh);   cudaGetSymbolAddress((void**)&aol, g_aol);
    cudaGetSymbolAddress((void**)&wdh, g_wdh);   cudaGetSymbolAddress((void**)&wdl, g_wdl);
    cudaGetSymbolAddress((void**)&wuh, g_wuh);   cudaGetSymbolAddress((void**)&wul, g_wul);
    cudaGetSymbolAddress((void**)&woh, g_woh);   cudaGetSymbolAddress((void**)&wol, g_wol);

    cudaFuncSetAttribute(mm_mma_kernel, cudaFuncAttributeMaxDynamicSharedMemorySize, MM_SMEM);
    cudaFuncSetAttribute(flashmma_kernel, cudaFuncAttributeMaxDynamicSharedMemorySize, FLASH_SMEM);

    // fused prep: weight transpose-splits + rope table + ssq zero
    prep_kernel<<<PB_TOTAL, 256>>>(W_DKV, W_DQ, W_KR, W_UK, W_UV, W_UQ, W_QR, W_O);

    // split x
    { int n = Msz * Dsz; split_kernel<<<(n / 8 + 255) / 256, 256>>>(x, xh, xl, n); }

    // fused down-projection (persistent): N=2176 -> bf16 ckvq + rope-K compact
    mm_mma_kernel<<<NSMS, 256, MM_SMEM>>>(
        xh, xl, xh, xl, 1 << 30, Dsz,
        wdh, wdl, nullptr, Msz, 2176, Dsz, /*epmode=*/1);

    // fused up-projection (persistent): N=7168 -> Kc, V, Qc, rope-Q
    mm_mma_kernel<<<NSMS, 256, MM_SMEM>>>(
        cvh, cvl, cvh + 1024, cvl + 1024, 4096, 2048,
        wuh, wul, nullptr, Msz, 7168, DCs, /*epmode=*/2);

    // norms
    norm_kernel<<<BNHL / 256, 256>>>(s_qk);

    // tensor-core causal flash attention -> aoh/aol
    flashmma_kernel<<<dim3(Lsz / FQ, NHs, Bsz), 256, FLASH_SMEM>>>();

    // output projection (persistent)
    mm_mma_kernel<<<NSMS, 256, MM_SMEM>>>(
        aoh, aol, aoh, aol, 1 << 30, Dsz,
        woh, wol, out, Msz, Dsz, Dsz, /*epmode=*/0);
}

// round 14
// speedup vs baseline: 1.1945x; 1.1945x over previous
#include <cuda_runtime.h>
#include <cuda_bf16.h>
#include <math.h>
#include <stdint.h>

// ---------------- problem constants ----------------
#define Bsz   4
#define Lsz   2048
#define Dsz   2048
#define NHs   16
#define DHs   128
#define DHRs  64
#define DCs   1024
#define DTOT  (DHs + DHRs)     // 192
#define Msz   (Bsz * Lsz)      // 8192
#define BNHL  (Bsz * NHs * Lsz)  // 131072

// ---------------- scratch ----------------
__device__ __align__(256) __nv_bfloat16 g_ckvqh[Msz * 2048];
__device__ __align__(256) __nv_bfloat16 g_ckvql[Msz * 2048];
__device__ __align__(256) __nv_bfloat16 g_aoh [Msz * Dsz];
__device__ __align__(256) __nv_bfloat16 g_aol [Msz * Dsz];
__device__ __align__(256) __nv_bfloat16 g_xh [Msz * Dsz];
__device__ __align__(256) __nv_bfloat16 g_xl [Msz * Dsz];
// attention operands (unnormalized; norm deferred to flash), hi/lo
__device__ __align__(256) __nv_bfloat16 g_Qch[BNHL * 128], g_Qcl[BNHL * 128];
__device__ __align__(256) __nv_bfloat16 g_Qrh[BNHL * 64],  g_Qrl[BNHL * 64];
__device__ __align__(256) __nv_bfloat16 g_Kch[BNHL * 128], g_Kcl[BNHL * 128];
__device__ __align__(256) __nv_bfloat16 g_krh[Msz * 64],   g_krl[Msz * 64];
__device__ __align__(256) __nv_bfloat16 g_Vh [BNHL * 128], g_Vl [BNHL * 128];
// norms
__device__ float g_ssqq[BNHL], g_ssqkc[BNHL], g_ssqkr[Msz];
__device__ float g_rq[BNHL], g_rk[BNHL];
__device__ float2 g_ropetab[Lsz * 32];
// stacked transposed weights [N x K] hi/lo
__device__ __align__(256) __nv_bfloat16 g_wdh[2176 * 2048], g_wdl[2176 * 2048];
__device__ __align__(256) __nv_bfloat16 g_wuh[7168 * 1024], g_wul[7168 * 1024];
__device__ __align__(256) __nv_bfloat16 g_woh[Dsz * Dsz],   g_wol[Dsz * Dsz];

#define LOG2_ROPE_BASE 13.287712379549449f

// ---------------- PTX helpers (baseline ISA only) ----------------
__device__ __forceinline__ uint32_t smem_u32(const void* p) {
    uint32_t a;
    asm("{ .reg .u64 t; cvta.to.shared.u64 t, %1; cvt.u32.u64 %0, t; }" : "=r"(a) : "l"(p));
    return a;
}
__device__ __forceinline__ void cpa16(uint32_t s, const void* g) {
    asm volatile("cp.async.cg.shared.global [%0], [%1], 16;" :: "r"(s), "l"(g) : "memory");
}
__device__ __forceinline__ void cp_commit() {
    asm volatile("cp.async.commit_group;" ::: "memory");
}
template <int N> __device__ __forceinline__ void cp_wait_group() {
    asm volatile("cp.async.wait_group %0;" :: "n"(N) : "memory");
}
__device__ __forceinline__ void ldm_x4(uint32_t* r, uint32_t addr) {
    asm volatile("ldmatrix.sync.aligned.m8n8.x4.shared.b16 {%0,%1,%2,%3}, [%4];"
                 : "=r"(r[0]), "=r"(r[1]), "=r"(r[2]), "=r"(r[3]) : "r"(addr));
}
__device__ __forceinline__ void ldm_x4_t(uint32_t* r, uint32_t addr) {
    asm volatile("ldmatrix.sync.aligned.m8n8.x4.trans.shared.b16 {%0,%1,%2,%3}, [%4];"
                 : "=r"(r[0]), "=r"(r[1]), "=r"(r[2]), "=r"(r[3]) : "r"(addr));
}
__device__ __forceinline__ void mma_bf16(float* c, const uint32_t* a, const uint32_t* b) {
    asm volatile(
        "mma.sync.aligned.m16n8k16.row.col.f32.bf16.bf16.f32 "
        "{%0,%1,%2,%3}, {%4,%5,%6,%7}, {%8,%9}, {%0,%1,%2,%3};"
        : "+f"(c[0]), "+f"(c[1]), "+f"(c[2]), "+f"(c[3])
        : "r"(a[0]), "r"(a[1]), "r"(a[2]), "r"(a[3]), "r"(b[0]), "r"(b[1]));
}
__device__ __forceinline__ uint32_t pack_bf162(float a, float b) {
    __nv_bfloat162 t;
    t.x = __float2bfloat16(a); t.y = __float2bfloat16(b);
    return *(uint32_t*)&t;
}
__device__ __forceinline__ void store_pair_hl(__nv_bfloat16* __restrict__ H,
                                              __nv_bfloat16* __restrict__ L,
                                              size_t o, float v0, float v1) {
    __nv_bfloat162 h2, l2;
    h2.x = __float2bfloat16(v0); h2.y = __float2bfloat16(v1);
    l2.x = __float2bfloat16(v0 - __bfloat162float(h2.x));
    l2.y = __float2bfloat16(v1 - __bfloat162float(h2.y));
    *(__nv_bfloat162*)&H[o] = h2;
    *(__nv_bfloat162*)&L[o] = l2;
}

// ---------------- fused prep: 8 weight tsplits + ropetab + ssq zero ----------------
#define PB_DKV 0
#define PB_DQ  2048
#define PB_KR  4096
#define PB_UK  4224
#define PB_UV  6272
#define PB_UQ  8320
#define PB_QR  10368
#define PB_WO  11392
#define PB_ROPE 15488
#define PB_ZERO (15488 + 256)
#define PB_TOTAL (PB_ZERO + BNHL / 256)

__global__ void __launch_bounds__(256)
prep_kernel(const float* __restrict__ Wdkv, const float* __restrict__ Wdq,
            const float* __restrict__ Wkr,  const float* __restrict__ Wuk,
            const float* __restrict__ Wuv,  const float* __restrict__ Wuq,
            const float* __restrict__ Wqr,  const float* __restrict__ Wo) {
    const int bid = blockIdx.x;
    const int tx = threadIdx.x & 31, ty = threadIdx.x >> 5;

    if (bid >= PB_ROPE) {
        int tid = ty * 32 + tx;
        if (bid < PB_ZERO) {
            int idx = (bid - PB_ROPE) * 256 + tid;
            int l = idx >> 5, i = idx & 31;
            float invf = exp2f(-(float)i * (LOG2_ROPE_BASE / 32.0f));
            float sn, cs;
            sincosf((float)l * invf, &sn, &cs);
            g_ropetab[idx] = make_float2(cs, sn);
        } else {
            int i = (bid - PB_ZERO) * 256 + tid;
            g_ssqq[i] = 0.f; g_ssqkc[i] = 0.f;
            if (i < Msz) g_ssqkr[i] = 0.f;
        }
        return;
    }

    const float* W; __nv_bfloat16 *Th, *Tl; int K, N, t;
    if (bid < PB_DQ)      { W = Wdkv; Th = g_wdh;                      Tl = g_wdl;                      K = 2048; N = 1024; t = bid; }
    else if (bid < PB_KR) { W = Wdq;  Th = g_wdh + (size_t)1024*2048;  Tl = g_wdl + (size_t)1024*2048;  K = 2048; N = 1024; t = bid - PB_DQ; }
    else if (bid < PB_UK) { W = Wkr;  Th = g_wdh + (size_t)2048*2048;  Tl = g_wdl + (size_t)2048*2048;  K = 2048; N = 64;   t = bid - PB_KR; }
    else if (bid < PB_UV) { W = Wuk;  Th = g_wuh;                      Tl = g_wul;                      K = 1024; N = 2048; t = bid - PB_UK; }
    else if (bid < PB_UQ) { W = Wuv;  Th = g_wuh + (size_t)2048*1024;  Tl = g_wul + (size_t)2048*1024;  K = 1024; N = 2048; t = bid - PB_UV; }
    else if (bid < PB_QR) { W = Wuq;  Th = g_wuh + (size_t)4096*1024;  Tl = g_wul + (size_t)4096*1024;  K = 1024; N = 2048; t = bid - PB_UQ; }
    else if (bid < PB_WO) { W = Wqr;  Th = g_wuh + (size_t)6144*1024;  Tl = g_wul + (size_t)6144*1024;  K = 1024; N = 1024; t = bid - PB_QR; }
    else                  { W = Wo;   Th = g_woh;                      Tl = g_wol;                      K = 2048; N = 2048; t = bid - PB_WO; }

    const int nbx = N >> 5;
    const int nb = (t % nbx) * 32;
    const int kb = (t / nbx) * 32;

    __shared__ float sh[32][33];
#pragma unroll
    for (int r = 0; r < 32; r += 8)
        sh[ty + r][tx] = W[(size_t)(kb + ty + r) * N + nb + tx];
    __syncthreads();
#pragma unroll
    for (int r = 0; r < 32; r += 8) {
        float x = sh[tx][ty + r];
        __nv_bfloat16 h = __float2bfloat16(x);
        float res = x - __bfloat162float(h);
        size_t o = (size_t)(nb + ty + r) * K + kb + tx;
        Th[o] = h;
        Tl[o] = __float2bfloat16(res);
    }
}

// ---------------- split x ----------------
__global__ void split_kernel(const float* __restrict__ src,
                             __nv_bfloat16* __restrict__ hi,
                             __nv_bfloat16* __restrict__ lo, int n) {
    int i0 = (blockIdx.x * 256 + threadIdx.x) * 8;
#pragma unroll
    for (int t = 0; t < 2; ++t) {
        int i = i0 + t * 4;
        if (i < n) {
            float4 v = *(const float4*)&src[i];
            __nv_bfloat162 h0, h1, l0, l1;
            h0.x = __float2bfloat16(v.x); h0.y = __float2bfloat16(v.y);
            h1.x = __float2bfloat16(v.z); h1.y = __float2bfloat16(v.w);
            l0.x = __float2bfloat16(v.x - __bfloat162float(h0.x));
            l0.y = __float2bfloat16(v.y - __bfloat162float(h0.y));
            l1.x = __float2bfloat16(v.z - __bfloat162float(h1.x));
            l1.y = __float2bfloat16(v.w - __bfloat162float(h1.y));
            *(__nv_bfloat162*)&hi[i]     = h0;
            *(__nv_bfloat162*)&hi[i + 2] = h1;
            *(__nv_bfloat162*)&lo[i]     = l0;
            *(__nv_bfloat162*)&lo[i + 2] = l1;
        }
    }
}

__global__ void norm_kernel(const float* __restrict__ s_qk_ptr) {
    int i = blockIdx.x * 256 + threadIdx.x;
    if (i >= BNHL) return;
    float s = *s_qk_ptr;
    int b = i >> 15, l = i & 2047;
    int bl = (b << 11) + l;
    g_rq[i] = s * rsqrtf(fmaxf(g_ssqq[i], 1e-24f));
    g_rk[i] = rsqrtf(fmaxf(g_ssqkc[i] + g_ssqkr[bl], 1e-24f));
}

// ---------------- mma.sync bf16 split-3 GEMM (4-stage, tiled grid — R12 proven config) ----------------
// CTA 256x128x32, 8 warps (4m x 2n), warp tile 64x64.
// epmode: 0 = fp32 Cf; 1 = down-proj (ckvq bf16 + rope-K); 2 = up-proj (Kc/V/Qc/rope-Q)
#define MMS_A_H 0
#define MMS_A_L 16384
#define MMS_B_H 32768
#define MMS_B_L 40960
#define MMS_STAGE 49152
#define MM_SMEM (4 * MMS_STAGE)   // 196608

__device__ __forceinline__ void mm_load_stage(
    uint32_t sbase,
    const __nv_bfloat16* __restrict__ Ah, const __nv_bfloat16* __restrict__ Al, int Astride,
    const __nv_bfloat16* __restrict__ Bh, const __nv_bfloat16* __restrict__ Bl,
    int m0, int n0, int k0, int Kd, int tid)
{
#pragma unroll
    for (int t = 0; t < 4; ++t) {
        int idx = tid + t * 256;
        int row = idx >> 2, c = idx & 3;
        uint32_t so = (uint32_t)(row * 64 + ((c ^ (row & 3)) << 4));
        size_t g = (size_t)(m0 + row) * Astride + k0 + c * 8;
        cpa16(sbase + MMS_A_H + so, Ah + g);
        cpa16(sbase + MMS_A_L + so, Al + g);
    }
#pragma unroll
    for (int t = 0; t < 2; ++t) {
        int idx = tid + t * 256;
        int row = idx >> 2, c = idx & 3;
        uint32_t so = (uint32_t)(row * 64 + ((c ^ (row & 3)) << 4));
        size_t g = (size_t)(n0 + row) * Kd + k0 + c * 8;
        cpa16(sbase + MMS_B_H + so, Bh + g);
        cpa16(sbase + MMS_B_L + so, Bl + g);
    }
}

__global__ void __launch_bounds__(256, 1)
mm_mma_kernel(const __nv_bfloat16* __restrict__ Ahg, const __nv_bfloat16* __restrict__ Alg,
              const __nv_bfloat16* __restrict__ Ahg2, const __nv_bfloat16* __restrict__ Alg2,
              int aswitch, int Astride,
              const __nv_bfloat16* __restrict__ Bhg, const __nv_bfloat16* __restrict__ Blg,
              float* __restrict__ Cf,
              int Nd, int Kd, int epmode) {
    extern __shared__ __align__(1024) char smem[];
    const uint32_t sb = smem_u32(smem);
    const int tid = threadIdx.x, wid = tid >> 5, lane = tid & 31;
    const int m0 = blockIdx.y * 256, n0 = blockIdx.x * 128;
    const int mw = (wid & 3) * 64;
    const int nw = (wid >> 2) * 64;

    const __nv_bfloat16* Auh = (n0 >= aswitch) ? Ahg2 : Ahg;
    const __nv_bfloat16* Aul = (n0 >= aswitch) ? Alg2 : Alg;

    float acc[4][8][4];
#pragma unroll
    for (int i = 0; i < 4; ++i)
#pragma unroll
        for (int j = 0; j < 8; ++j)
#pragma unroll
            for (int q = 0; q < 4; ++q) acc[i][j][q] = 0.f;

    const int nk = Kd >> 5;
#pragma unroll
    for (int s = 0; s < 3; ++s) {
        mm_load_stage(sb + s * MMS_STAGE, Auh, Aul, Astride, Bhg, Blg, m0, n0, s << 5, Kd, tid);
        cp_commit();
    }

    const int jA = lane >> 3, rA = lane & 7;

    int sidx = 0;
    for (int it = 0; it < nk; ++it) {
        cp_wait_group<2>();
        __syncthreads();

        if (it + 3 < nk) {
            int ps = sidx + 3; if (ps >= 4) ps -= 4;
            mm_load_stage(sb + ps * MMS_STAGE, Auh, Aul, Astride, Bhg, Blg,
                          m0, n0, (it + 3) << 5, Kd, tid);
        }
        cp_commit();

        const uint32_t stg = sb + sidx * MMS_STAGE;

#pragma unroll
        for (int ks = 0; ks < 2; ++ks) {
            uint32_t ah[4][4], al[4][4];
#pragma unroll
            for (int i = 0; i < 4; ++i) {
                int m = mw + i * 16 + ((jA & 1) << 3) + rA;
                int c = (ks << 1) + (jA >> 1);
                uint32_t off = (uint32_t)(m * 64 + ((c ^ (m & 3)) << 4));
                ldm_x4(ah[i], stg + MMS_A_H + off);
                ldm_x4(al[i], stg + MMS_A_L + off);
            }
            uint32_t bh[8][2], bl[8][2];
#pragma unroll
            for (int p = 0; p < 4; ++p) {
                int n = nw + p * 16 + ((jA >> 1) << 3) + rA;
                int c = (ks << 1) + (jA & 1);
                uint32_t off = (uint32_t)(n * 64 + ((c ^ (n & 3)) << 4));
                uint32_t tmp[4];
                ldm_x4(tmp, stg + MMS_B_H + off);
                bh[2 * p][0] = tmp[0]; bh[2 * p][1] = tmp[1];
                bh[2 * p + 1][0] = tmp[2]; bh[2 * p + 1][1] = tmp[3];
                ldm_x4(tmp, stg + MMS_B_L + off);
                bl[2 * p][0] = tmp[0]; bl[2 * p][1] = tmp[1];
                bl[2 * p + 1][0] = tmp[2]; bl[2 * p + 1][1] = tmp[3];
            }
#pragma unroll
            for (int i = 0; i < 4; ++i)
#pragma unroll
                for (int j = 0; j < 8; ++j) {
                    mma_bf16(acc[i][j], ah[i], bh[j]);
                    mma_bf16(acc[i][j], al[i], bh[j]);
                    mma_bf16(acc[i][j], ah[i], bl[j]);
                }
        }
        if (++sidx == 4) sidx = 0;
    }

    // ================= epilogues =================
    if (epmode == 0) {
#pragma unroll
        for (int i = 0; i < 4; ++i) {
            int row = m0 + mw + i * 16 + (lane >> 2);
#pragma unroll
            for (int j = 0; j < 8; ++j) {
                int col = n0 + nw + j * 8 + ((lane & 3) << 1);
                *(float2*)&Cf[(size_t)row * Nd + col]       = make_float2(acc[i][j][0], acc[i][j][1]);
                *(float2*)&Cf[(size_t)(row + 8) * Nd + col] = make_float2(acc[i][j][2], acc[i][j][3]);
            }
        }
    } else if (epmode == 1) {
        if (n0 < 2048) {
#pragma unroll
            for (int i = 0; i < 4; ++i) {
                int row = m0 + mw + i * 16 + (lane >> 2);
#pragma unroll
                for (int j = 0; j < 8; ++j) {
                    int col = n0 + nw + j * 8 + ((lane & 3) << 1);
                    store_pair_hl(g_ckvqh, g_ckvql, (size_t)row * 2048 + col, acc[i][j][0], acc[i][j][1]);
                    store_pair_hl(g_ckvqh, g_ckvql, (size_t)(row + 8) * 2048 + col, acc[i][j][2], acc[i][j][3]);
                }
            }
        } else if (nw == 0) {
            // rope-K: cols 2048..2111 -> dr 0..63
#pragma unroll
            for (int i = 0; i < 4; ++i) {
                int rbase = m0 + mw + i * 16 + (lane >> 2);
#pragma unroll
                for (int hh = 0; hh < 2; ++hh) {
                    int rr = rbase + hh * 8;
                    int l = rr & 2047;
                    float ssq = 0.f;
                    float o0[8], o1[8];
#pragma unroll
                    for (int j = 0; j < 8; ++j) {
                        float x1a = acc[i][j][2 * hh], x1b = acc[i][j][2 * hh + 1];
                        int jp = j ^ 4;
                        float sgn = (j < 4) ? -1.f : 1.f;
                        float x2a = acc[i][jp][2 * hh], x2b = acc[i][jp][2 * hh + 1];
                        int i0 = ((j & 3) << 3) + ((lane & 3) << 1);
                        float2 cs0 = g_ropetab[(l << 5) + i0];
                        float2 cs1 = g_ropetab[(l << 5) + i0 + 1];
                        o0[j] = x1a * cs0.x + sgn * x2a * cs0.y;
                        o1[j] = x1b * cs1.x + sgn * x2b * cs1.y;
                        ssq += x1a * x1a + x1b * x1b;
                    }
                    ssq += __shfl_xor_sync(0xffffffffu, ssq, 1);
                    ssq += __shfl_xor_sync(0xffffffffu, ssq, 2);
                    if ((lane & 3) == 0) atomicAdd(&g_ssqkr[rr], ssq);
#pragma unroll
                    for (int j = 0; j < 8; ++j) {
                        int dr = (j << 3) + ((lane & 3) << 1);
                        store_pair_hl(g_krh, g_krl, (size_t)rr * 64 + dr, o0[j], o1[j]);
                    }
                }
            }
        }
    } else {
        int region = n0 >> 11;        // 0 UK, 1 UV, 2 UQ, 3 QR
        if (region < 3) {
            int cbase = (n0 + nw) & 2047;
            int h = cbase >> 7, dbase = cbase & 127;
#pragma unroll
            for (int i = 0; i < 4; ++i) {
                int rbase = m0 + mw + i * 16 + (lane >> 2);
#pragma unroll
                for (int hh = 0; hh < 2; ++hh) {
                    int rr = rbase + hh * 8;
                    int bb = rr >> 11, l = rr & 2047;
                    size_t hidx = (size_t)(bb * NHs + h) * 2048 + l;
                    size_t hb = hidx * 128 + dbase;
                    float ssq = 0.f;
#pragma unroll
                    for (int j = 0; j < 8; ++j) {
                        float v0 = acc[i][j][2 * hh], v1 = acc[i][j][2 * hh + 1];
                        int d = (j << 3) + ((lane & 3) << 1);
                        if (region == 0)      store_pair_hl(g_Kch, g_Kcl, hb + d, v0, v1);
                        else if (region == 1) store_pair_hl(g_Vh,  g_Vl,  hb + d, v0, v1);
                        else                  store_pair_hl(g_Qch, g_Qcl, hb + d, v0, v1);
                        ssq += v0 * v0 + v1 * v1;
                    }
                    if (region != 1) {
                        ssq += __shfl_xor_sync(0xffffffffu, ssq, 1);
                        ssq += __shfl_xor_sync(0xffffffffu, ssq, 2);
                        if ((lane & 3) == 0)
                            atomicAdd(region == 0 ? &g_ssqkc[hidx] : &g_ssqq[hidx], ssq);
                    }
                }
            }
        } else {
            int local0 = (n0 - 6144) + nw;
            int h = local0 >> 6;
#pragma unroll
            for (int i = 0; i < 4; ++i) {
                int rbase = m0 + mw + i * 16 + (lane >> 2);
#pragma unroll
                for (int hh = 0; hh < 2; ++hh) {
                    int rr = rbase + hh * 8;
                    int bb = rr >> 11, l = rr & 2047;
                    size_t hidx = (size_t)(bb * NHs + h) * 2048 + l;
                    float ssq = 0.f;
                    float o0[8], o1[8];
#pragma unroll
                    for (int j = 0; j < 8; ++j) {
                        float x1a = acc[i][j][2 * hh], x1b = acc[i][j][2 * hh + 1];
                        int jp = j ^ 4;
                        float sgn = (j < 4) ? -1.f : 1.f;
                        float x2a = acc[i][jp][2 * hh], x2b = acc[i][jp][2 * hh + 1];
                        int i0 = ((j & 3) << 3) + ((lane & 3) << 1);
                        float2 cs0 = g_ropetab[(l << 5) + i0];
                        float2 cs1 = g_ropetab[(l << 5) + i0 + 1];
                        o0[j] = x1a * cs0.x + sgn * x2a * cs0.y;
                        o1[j] = x1b * cs1.x + sgn * x2b * cs1.y;
                        ssq += x1a * x1a + x1b * x1b;
                    }
                    ssq += __shfl_xor_sync(0xffffffffu, ssq, 1);
                    ssq += __shfl_xor_sync(0xffffffffu, ssq, 2);
                    if ((lane & 3) == 0) atomicAdd(&g_ssqq[hidx], ssq);
#pragma unroll
                    for (int j = 0; j < 8; ++j) {
                        int dr = (j << 3) + ((lane & 3) << 1);
                        store_pair_hl(g_Qrh, g_Qrl, hidx * 64 + dr, o0[j], o1[j]);
                    }
                }
            }
        }
    }
}

// ---------------- tensor-core causal flash attention (split-3 bf16, register P, deferred norm) ----------------
#define FQ 128
#define FK 64
#define SQH 0
#define SQL (SQH + FQ*384)
#define SKH (SQL + FQ*384)
#define SKL (SKH + FK*384)
#define SV0H (SKL + FK*384)
#define SV0L (SV0H + FK*256)
#define SV1H (SV0L + FK*256)
#define SV1L (SV1H + FK*256)
#define FLASH_SMEM (SV1L + FK*256)   // 212992

__device__ __forceinline__ void fl_load_q(uint32_t sb, int b, int h, int q0, int tid) {
    size_t cb = (size_t)(b * NHs + h) * Lsz + q0;
    for (int idx = tid; idx < FQ * 24; idx += 256) {
        int r = idx / 24, c = idx % 24;
        uint32_t so = (uint32_t)(r * 384 + ((c ^ (r & 7)) << 4));
        if (c < 16) {
            size_t g = (cb + r) * 128 + c * 8;
            cpa16(sb + SQH + so, g_Qch + g);
            cpa16(sb + SQL + so, g_Qcl + g);
        } else {
            size_t g = (cb + r) * 64 + (c - 16) * 8;
            cpa16(sb + SQH + so, g_Qrh + g);
            cpa16(sb + SQL + so, g_Qrl + g);
        }
    }
}
__device__ __forceinline__ void fl_load_k(uint32_t sb, int b, int h, int k0, int tid) {
    size_t cb = (size_t)(b * NHs + h) * Lsz + k0;
    size_t rb = (size_t)b * Lsz + k0;
    for (int idx = tid; idx < FK * 24; idx += 256) {
        int r = idx / 24, c = idx % 24;
        uint32_t so = (uint32_t)(r * 384 + ((c ^ (r & 7)) << 4));
        if (c < 16) {
            size_t g = (cb + r) * 128 + c * 8;
            cpa16(sb + SKH + so, g_Kch + g);
            cpa16(sb + SKL + so, g_Kcl + g);
        } else {
            size_t g = (rb + r) * 64 + (c - 16) * 8;
            cpa16(sb + SKH + so, g_krh + g);
            cpa16(sb + SKL + so, g_krl + g);
        }
    }
}
__device__ __forceinline__ void fl_load_v(uint32_t sb, uint32_t vH, uint32_t vL,
                                          int b, int h, int k0, int tid) {
    size_t gb = ((size_t)(b * NHs + h) * Lsz + k0) * DHs;
    for (int idx = tid; idx < FK * 16; idx += 256) {
        int r = idx >> 4, c = idx & 15;
        uint32_t so = (uint32_t)(r * 256 + ((c ^ (r & 7)) << 4));
        size_t g = gb + (size_t)r * DHs + c * 8;
        cpa16(sb + vH + so, g_Vh + g);
        cpa16(sb + vL + so, g_Vl + g);
    }
}

__global__ void __launch_bounds__(256, 1)
flashmma_kernel() {
    extern __shared__ __align__(1024) char sm[];
    const uint32_t sb = smem_u32(sm);
    const int tid = threadIdx.x, w = tid >> 5, lane = tid & 31;
    const int qt = (int)(gridDim.x - 1u - blockIdx.x);
    const int h = blockIdx.y, b = blockIdx.z;
    const int q0 = qt * FQ;
    const int mw = w * 16;
    const int jA = lane >> 3, rA = lane & 7;

    fl_load_q(sb, b, h, q0, tid);
    cp_commit();
    fl_load_k(sb, b, h, 0, tid);
    fl_load_v(sb, SV0H, SV0L, b, h, 0, tid);
    cp_commit();

    float oacc[16][4];
#pragma unroll
    for (int j = 0; j < 16; ++j)
#pragma unroll
        for (int q = 0; q < 4; ++q) oacc[j][q] = 0.f;
    float m0 = -1e30f, m1 = -1e30f, l0 = 0.f, l1 = 0.f;

    const int nkt = 2 * qt + 2;
    const int r0loc = mw + (lane >> 2);
    const int gr0 = q0 + r0loc;

    const float* rqb = g_rq + (size_t)(b * NHs + h) * Lsz;
    const float* rkb = g_rk + (size_t)(b * NHs + h) * Lsz;
    const float rq0 = rqb[gr0], rq1 = rqb[gr0 + 8];

    for (int kt = 0; kt < nkt; ++kt) {
        const int k0 = kt * FK;
        float2 rkv[8];
#pragma unroll
        for (int j = 0; j < 8; ++j)
            rkv[j] = *(const float2*)&rkb[k0 + j * 8 + ((lane & 3) << 1)];

        cp_wait_group<0>();
        __syncthreads();

        // V(kt+1) issued EARLY (double-buffered; target buffer was consumed in iter kt-1)
        if (kt + 1 < nkt) {
            uint32_t vH = ((kt + 1) & 1) ? SV1H : SV0H;
            uint32_t vL = ((kt + 1) & 1) ? SV1L : SV0L;
            fl_load_v(sb, vH, vL, b, h, (kt + 1) * FK, tid);
        }
        cp_commit();

        // ---- S = Q K^T (split-3, unnormalized) ----
        float sacc[8][4];
#pragma unroll
        for (int j = 0; j < 8; ++j)
#pragma unroll
            for (int q = 0; q < 4; ++q) sacc[j][q] = 0.f;

#pragma unroll
        for (int ks = 0; ks < 12; ++ks) {
            int arow = mw + ((jA & 1) << 3) + rA;
            int achk = ks * 2 + (jA >> 1);
            uint32_t aoff = (uint32_t)(arow * 384 + ((achk ^ (arow & 7)) << 4));
            uint32_t ah[4], al[4];
            ldm_x4(ah, sb + SQH + aoff);
            ldm_x4(al, sb + SQL + aoff);
            uint32_t bh[8][2], bl[8][2];
#pragma unroll
            for (int p = 0; p < 4; ++p) {
                int brow = p * 16 + ((jA >> 1) << 3) + rA;
                int bchk = ks * 2 + (jA & 1);
                uint32_t boff = (uint32_t)(brow * 384 + ((bchk ^ (brow & 7)) << 4));
                uint32_t tmp[4];
                ldm_x4(tmp, sb + SKH + boff);
                bh[2 * p][0] = tmp[0]; bh[2 * p][1] = tmp[1];
                bh[2 * p + 1][0] = tmp[2]; bh[2 * p + 1][1] = tmp[3];
                ldm_x4(tmp, sb + SKL + boff);
                bl[2 * p][0] = tmp[0]; bl[2 * p][1] = tmp[1];
                bl[2 * p + 1][0] = tmp[2]; bl[2 * p + 1][1] = tmp[3];
            }
#pragma unroll
            for (int j = 0; j < 8; ++j) {
                mma_bf16(sacc[j], ah, bh[j]);
                mma_bf16(sacc[j], al, bh[j]);
                mma_bf16(sacc[j], ah, bl[j]);
            }
        }

        // ---- deferred normalization: S *= rq_row * rk_col ----
#pragma unroll
        for (int j = 0; j < 8; ++j) {
            sacc[j][0] *= rq0 * rkv[j].x;
            sacc[j][1] *= rq0 * rkv[j].y;
            sacc[j][2] *= rq1 * rkv[j].x;
            sacc[j][3] *= rq1 * rkv[j].y;
        }

        // ---- causal mask (last two k-tiles only) ----
        if (kt >= 2 * qt) {
#pragma unroll
            for (int j = 0; j < 8; ++j) {
                int col = k0 + j * 8 + ((lane & 3) << 1);
                if (col > gr0)     sacc[j][0] = -1e30f;
                if (col + 1 > gr0) sacc[j][1] = -1e30f;
                if (col > gr0 + 8)     sacc[j][2] = -1e30f;
                if (col + 1 > gr0 + 8) sacc[j][3] = -1e30f;
            }
        }

        // ---- online softmax (register P, hi/lo fragments) ----
        float mx0 = -1e30f, mx1 = -1e30f;
#pragma unroll
        for (int j = 0; j < 8; ++j) {
            mx0 = fmaxf(mx0, fmaxf(sacc[j][0], sacc[j][1]));
            mx1 = fmaxf(mx1, fmaxf(sacc[j][2], sacc[j][3]));
        }
#pragma unroll
        for (int o = 1; o <= 2; o <<= 1) {
            mx0 = fmaxf(mx0, __shfl_xor_sync(0xffffffffu, mx0, o));
            mx1 = fmaxf(mx1, __shfl_xor_sync(0xffffffffu, mx1, o));
        }
        float mn0 = fmaxf(m0, mx0), mn1 = fmaxf(m1, mx1);
        float sc0 = __expf(m0 - mn0), sc1 = __expf(m1 - mn1);
        m0 = mn0; m1 = mn1;

        uint32_t pfh[4][4], pfl[4][4];
        float rs0 = 0.f, rs1 = 0.f;
#pragma unroll
        for (int j = 0; j < 8; ++j) {
            float p0 = __expf(sacc[j][0] - mn0);
            float p1 = __expf(sacc[j][1] - mn0);
            float p2 = __expf(sacc[j][2] - mn1);
            float p3 = __expf(sacc[j][3] - mn1);
            rs0 += p0 + p1; rs1 += p2 + p3;
            __nv_bfloat162 h01, h23;
            h01.x = __float2bfloat16(p0); h01.y = __float2bfloat16(p1);
            h23.x = __float2bfloat16(p2); h23.y = __float2bfloat16(p3);
            int t = j >> 1, s = (j & 1) * 2;
            pfh[t][s + 0] = *(uint32_t*)&h01;
            pfh[t][s + 1] = *(uint32_t*)&h23;
            pfl[t][s + 0] = pack_bf162(p0 - __bfloat162float(h01.x),
                                       p1 - __bfloat162float(h01.y));
            pfl[t][s + 1] = pack_bf162(p2 - __bfloat162float(h23.x),
                                       p3 - __bfloat162float(h23.y));
        }
#pragma unroll
        for (int o = 1; o <= 2; o <<= 1) {
            rs0 += __shfl_xor_sync(0xffffffffu, rs0, o);
            rs1 += __shfl_xor_sync(0xffffffffu, rs1, o);
        }
        l0 = l0 * sc0 + rs0;
        l1 = l1 * sc1 + rs1;
#pragma unroll
        for (int j = 0; j < 16; ++j) {
            oacc[j][0] *= sc0; oacc[j][1] *= sc0;
            oacc[j][2] *= sc1; oacc[j][3] *= sc1;
        }

        __syncthreads();                // all warps done reading K(kt)

        if (kt + 1 < nkt)
            fl_load_k(sb, b, h, (kt + 1) * FK, tid);
        cp_commit();

        // ---- O += P V (split-3), V from buffer kt&1, P from registers ----
        const uint32_t vH = (kt & 1) ? SV1H : SV0H;
        const uint32_t vL = (kt & 1) ? SV1L : SV0L;
#pragma unroll
        for (int ks = 0; ks < 4; ++ks) {
            int key = ks * 16 + (lane & 15);
#pragma unroll
            for (int p = 0; p < 8; ++p) {
                int dch = p * 2 + (lane >> 4);
                uint32_t voff = (uint32_t)(key * 256 + ((dch ^ (key & 7)) << 4));
                uint32_t th[4], tl[4];
                ldm_x4_t(th, sb + vH + voff);
                ldm_x4_t(tl, sb + vL + voff);
                mma_bf16(oacc[2 * p], pfh[ks], th);
                mma_bf16(oacc[2 * p], pfl[ks], th);
                mma_bf16(oacc[2 * p], pfh[ks], tl);
                mma_bf16(oacc[2 * p + 1], pfh[ks], th + 2);
                mma_bf16(oacc[2 * p + 1], pfl[ks], th + 2);
                mma_bf16(oacc[2 * p + 1], pfh[ks], tl + 2);
            }
        }
    }

    // ---- epilogue: normalize, split, write (B,L,D) bf16 hi/lo ----
    float inv0 = 1.0f / l0, inv1 = 1.0f / l1;
    size_t ob0 = ((size_t)(b * Lsz + gr0)) * Dsz + h * DHs;
    size_t ob1 = ((size_t)(b * Lsz + gr0 + 8)) * Dsz + h * DHs;
#pragma unroll
    for (int j = 0; j < 16; ++j) {
        int d = j * 8 + ((lane & 3) << 1);
        store_pair_hl(g_aoh, g_aol, ob0 + d, oacc[j][0] * inv0, oacc[j][1] * inv0);
        store_pair_hl(g_aoh, g_aol, ob1 + d, oacc[j][2] * inv1, oacc[j][3] * inv1);
    }
}

// ---------------- launcher ----------------
extern "C" void kernel_launch(void* const* d_in, const int* in_sizes, int n_in,
                              void* d_out, int out_size) {
    const float* x     = (const float*)d_in[0];
    const float* W_DKV = (const float*)d_in[1];
    const float* W_UK  = (const float*)d_in[2];
    const float* W_UV  = (const float*)d_in[3];
    const float* W_DQ  = (const float*)d_in[4];
    const float* W_UQ  = (const float*)d_in[5];
    const float* W_QR  = (const float*)d_in[6];
    const float* W_KR  = (const float*)d_in[7];
    const float* W_O   = (const float*)d_in[8];
    const float* s_qk  = (const float*)d_in[9];
    float* out = (float*)d_out;

    __nv_bfloat16 *xh, *xl, *cvh, *cvl, *aoh, *aol;
    __nv_bfloat16 *wdh, *wdl, *wuh, *wul, *woh, *wol;
    cudaGetSymbolAddress((void**)&xh, g_xh);     cudaGetSymbolAddress((void**)&xl, g_xl);
    cudaGetSymbolAddress((void**)&cvh, g_ckvqh); cudaGetSymbolAddress((void**)&cvl, g_ckvql);
    cudaGetSymbolAddress((void**)&aoh, g_aoh);   cudaGetSymbolAddress((void**)&aol, g_aol);
    cudaGetSymbolAddress((void**)&wdh, g_wdh);   cudaGetSymbolAddress((void**)&wdl, g_wdl);
    cudaGetSymbolAddress((void**)&wuh, g_wuh);   cudaGetSymbolAddress((void**)&wul, g_wul);
    cudaGetSymbolAddress((void**)&woh, g_woh);   cudaGetSymbolAddress((void**)&wol, g_wol);

    cudaFuncSetAttribute(mm_mma_kernel, cudaFuncAttributeMaxDynamicSharedMemorySize, MM_SMEM);
    cudaFuncSetAttribute(flashmma_kernel, cudaFuncAttributeMaxDynamicSharedMemorySize, FLASH_SMEM);

    // fused prep: weight transpose-splits + rope table + ssq zero
    prep_kernel<<<PB_TOTAL, 256>>>(W_DKV, W_DQ, W_KR, W_UK, W_UV, W_UQ, W_QR, W_O);

    // split x
    { int n = Msz * Dsz; split_kernel<<<(n / 8 + 255) / 256, 256>>>(x, xh, xl, n); }

    // fused down-projection: N=2176 -> bf16 ckvq + rope-K compact
    mm_mma_kernel<<<dim3(2176/128, Msz/256), 256, MM_SMEM>>>(
        xh, xl, xh, xl, 1 << 30, Dsz,
        wdh, wdl, nullptr, 2176, Dsz, /*epmode=*/1);

    // fused up-projection: N=7168 -> Kc, V, Qc, rope-Q (attention layout, bf16 hi/lo)
    mm_mma_kernel<<<dim3(7168/128, Msz/256), 256, MM_SMEM>>>(
        cvh, cvl, cvh + 1024, cvl + 1024, 4096, 2048,
        wuh, wul, nullptr, 7168, DCs, /*epmode=*/2);

    // norms
    norm_kernel<<<BNHL / 256, 256>>>(s_qk);

    // tensor-core causal flash attention -> aoh/aol
    flashmma_kernel<<<dim3(Lsz / FQ, NHs, Bsz), 256, FLASH_SMEM>>>();

    // output projection
    mm_mma_kernel<<<dim3(Dsz/128, Msz/256), 256, MM_SMEM>>>(
        aoh, aol, aoh, aol, 1 << 30, Dsz,
        woh, wol, out, Dsz, Dsz, /*epmode=*/0);
}

// round 16
// speedup vs baseline: 1.1989x; 1.0037x over previous
#include <cuda_runtime.h>
#include <cuda_bf16.h>
#include <math.h>
#include <stdint.h>

// ---------------- problem constants ----------------
#define Bsz   4
#define Lsz   2048
#define Dsz   2048
#define NHs   16
#define DHs   128
#define DHRs  64
#define DCs   1024
#define DTOT  (DHs + DHRs)     // 192
#define Msz   (Bsz * Lsz)      // 8192
#define BNHL  (Bsz * NHs * Lsz)  // 131072

// ---------------- scratch ----------------
__device__ __align__(256) __nv_bfloat16 g_ckvqh[Msz * 2048];
__device__ __align__(256) __nv_bfloat16 g_ckvql[Msz * 2048];
__device__ __align__(256) __nv_bfloat16 g_aoh [Msz * Dsz];
__device__ __align__(256) __nv_bfloat16 g_aol [Msz * Dsz];
__device__ __align__(256) __nv_bfloat16 g_xh [Msz * Dsz];
__device__ __align__(256) __nv_bfloat16 g_xl [Msz * Dsz];
// attention operands (unnormalized; norm deferred to flash), hi/lo
__device__ __align__(256) __nv_bfloat16 g_Qch[BNHL * 128], g_Qcl[BNHL * 128];
__device__ __align__(256) __nv_bfloat16 g_Qrh[BNHL * 64],  g_Qrl[BNHL * 64];
__device__ __align__(256) __nv_bfloat16 g_Kch[BNHL * 128], g_Kcl[BNHL * 128];
__device__ __align__(256) __nv_bfloat16 g_krh[Msz * 64],   g_krl[Msz * 64];
__device__ __align__(256) __nv_bfloat16 g_Vh [BNHL * 128], g_Vl [BNHL * 128];
// norms
__device__ float g_ssqq[BNHL], g_ssqkc[BNHL], g_ssqkr[Msz];
__device__ float g_rq[BNHL], g_rk[BNHL];
__device__ float2 g_ropetab[Lsz * 32];
// stacked transposed weights [N x K] hi/lo
__device__ __align__(256) __nv_bfloat16 g_wdh[2176 * 2048], g_wdl[2176 * 2048];
__device__ __align__(256) __nv_bfloat16 g_wuh[7168 * 1024], g_wul[7168 * 1024];
__device__ __align__(256) __nv_bfloat16 g_woh[Dsz * Dsz],   g_wol[Dsz * Dsz];

#define LOG2_ROPE_BASE 13.287712379549449f

// ---------------- PTX helpers (baseline ISA only) ----------------
__device__ __forceinline__ uint32_t smem_u32(const void* p) {
    uint32_t a;
    asm("{ .reg .u64 t; cvta.to.shared.u64 t, %1; cvt.u32.u64 %0, t; }" : "=r"(a) : "l"(p));
    return a;
}
__device__ __forceinline__ void cpa16(uint32_t s, const void* g) {
    asm volatile("cp.async.cg.shared.global [%0], [%1], 16;" :: "r"(s), "l"(g) : "memory");
}
__device__ __forceinline__ void cp_commit() {
    asm volatile("cp.async.commit_group;" ::: "memory");
}
template <int N> __device__ __forceinline__ void cp_wait_group() {
    asm volatile("cp.async.wait_group %0;" :: "n"(N) : "memory");
}
__device__ __forceinline__ void ldm_x4(uint32_t* r, uint32_t addr) {
    asm volatile("ldmatrix.sync.aligned.m8n8.x4.shared.b16 {%0,%1,%2,%3}, [%4];"
                 : "=r"(r[0]), "=r"(r[1]), "=r"(r[2]), "=r"(r[3]) : "r"(addr));
}
__device__ __forceinline__ void ldm_x4_t(uint32_t* r, uint32_t addr) {
    asm volatile("ldmatrix.sync.aligned.m8n8.x4.trans.shared.b16 {%0,%1,%2,%3}, [%4];"
                 : "=r"(r[0]), "=r"(r[1]), "=r"(r[2]), "=r"(r[3]) : "r"(addr));
}
__device__ __forceinline__ void mma_bf16(float* c, const uint32_t* a, const uint32_t* b) {
    asm volatile(
        "mma.sync.aligned.m16n8k16.row.col.f32.bf16.bf16.f32 "
        "{%0,%1,%2,%3}, {%4,%5,%6,%7}, {%8,%9}, {%0,%1,%2,%3};"
        : "+f"(c[0]), "+f"(c[1]), "+f"(c[2]), "+f"(c[3])
        : "r"(a[0]), "r"(a[1]), "r"(a[2]), "r"(a[3]), "r"(b[0]), "r"(b[1]));
}
__device__ __forceinline__ uint32_t pack_bf162(float a, float b) {
    __nv_bfloat162 t;
    t.x = __float2bfloat16(a); t.y = __float2bfloat16(b);
    return *(uint32_t*)&t;
}
__device__ __forceinline__ void store_pair_hl(__nv_bfloat16* __restrict__ H,
                                              __nv_bfloat16* __restrict__ L,
                                              size_t o, float v0, float v1) {
    __nv_bfloat162 h2, l2;
    h2.x = __float2bfloat16(v0); h2.y = __float2bfloat16(v1);
    l2.x = __float2bfloat16(v0 - __bfloat162float(h2.x));
    l2.y = __float2bfloat16(v1 - __bfloat162float(h2.y));
    *(__nv_bfloat162*)&H[o] = h2;
    *(__nv_bfloat162*)&L[o] = l2;
}

// ---------------- fused prep: 8 weight tsplits + ropetab + ssq zero ----------------
#define PB_DKV 0
#define PB_DQ  2048
#define PB_KR  4096
#define PB_UK  4224
#define PB_UV  6272
#define PB_UQ  8320
#define PB_QR  10368
#define PB_WO  11392
#define PB_ROPE 15488
#define PB_ZERO (15488 + 256)
#define PB_TOTAL (PB_ZERO + BNHL / 256)

__global__ void __launch_bounds__(256)
prep_kernel(const float* __restrict__ Wdkv, const float* __restrict__ Wdq,
            const float* __restrict__ Wkr,  const float* __restrict__ Wuk,
            const float* __restrict__ Wuv,  const float* __restrict__ Wuq,
            const float* __restrict__ Wqr,  const float* __restrict__ Wo) {
    const int bid = blockIdx.x;
    const int tx = threadIdx.x & 31, ty = threadIdx.x >> 5;

    if (bid >= PB_ROPE) {
        int tid = ty * 32 + tx;
        if (bid < PB_ZERO) {
            int idx = (bid - PB_ROPE) * 256 + tid;
            int l = idx >> 5, i = idx & 31;
            float invf = exp2f(-(float)i * (LOG2_ROPE_BASE / 32.0f));
            float sn, cs;
            sincosf((float)l * invf, &sn, &cs);
            g_ropetab[idx] = make_float2(cs, sn);
        } else {
            int i = (bid - PB_ZERO) * 256 + tid;
            g_ssqq[i] = 0.f; g_ssqkc[i] = 0.f;
            if (i < Msz) g_ssqkr[i] = 0.f;
        }
        return;
    }

    const float* W; __nv_bfloat16 *Th, *Tl; int K, N, t;
    if (bid < PB_DQ)      { W = Wdkv; Th = g_wdh;                      Tl = g_wdl;                      K = 2048; N = 1024; t = bid; }
    else if (bid < PB_KR) { W = Wdq;  Th = g_wdh + (size_t)1024*2048;  Tl = g_wdl + (size_t)1024*2048;  K = 2048; N = 1024; t = bid - PB_DQ; }
    else if (bid < PB_UK) { W = Wkr;  Th = g_wdh + (size_t)2048*2048;  Tl = g_wdl + (size_t)2048*2048;  K = 2048; N = 64;   t = bid - PB_KR; }
    else if (bid < PB_UV) { W = Wuk;  Th = g_wuh;                      Tl = g_wul;                      K = 1024; N = 2048; t = bid - PB_UK; }
    else if (bid < PB_UQ) { W = Wuv;  Th = g_wuh + (size_t)2048*1024;  Tl = g_wul + (size_t)2048*1024;  K = 1024; N = 2048; t = bid - PB_UV; }
    else if (bid < PB_QR) { W = Wuq;  Th = g_wuh + (size_t)4096*1024;  Tl = g_wul + (size_t)4096*1024;  K = 1024; N = 2048; t = bid - PB_UQ; }
    else if (bid < PB_WO) { W = Wqr;  Th = g_wuh + (size_t)6144*1024;  Tl = g_wul + (size_t)6144*1024;  K = 1024; N = 1024; t = bid - PB_QR; }
    else                  { W = Wo;   Th = g_woh;                      Tl = g_wol;                      K = 2048; N = 2048; t = bid - PB_WO; }

    const int nbx = N >> 5;
    const int nb = (t % nbx) * 32;
    const int kb = (t / nbx) * 32;

    __shared__ float sh[32][33];
#pragma unroll
    for (int r = 0; r < 32; r += 8)
        sh[ty + r][tx] = W[(size_t)(kb + ty + r) * N + nb + tx];
    __syncthreads();
#pragma unroll
    for (int r = 0; r < 32; r += 8) {
        float x = sh[tx][ty + r];
        __nv_bfloat16 h = __float2bfloat16(x);
        float res = x - __bfloat162float(h);
        size_t o = (size_t)(nb + ty + r) * K + kb + tx;
        Th[o] = h;
        Tl[o] = __float2bfloat16(res);
    }
}

// ---------------- split x ----------------
__global__ void split_kernel(const float* __restrict__ src,
                             __nv_bfloat16* __restrict__ hi,
                             __nv_bfloat16* __restrict__ lo, int n) {
    int i0 = (blockIdx.x * 256 + threadIdx.x) * 8;
#pragma unroll
    for (int t = 0; t < 2; ++t) {
        int i = i0 + t * 4;
        if (i < n) {
            float4 v = *(const float4*)&src[i];
            __nv_bfloat162 h0, h1, l0, l1;
            h0.x = __float2bfloat16(v.x); h0.y = __float2bfloat16(v.y);
            h1.x = __float2bfloat16(v.z); h1.y = __float2bfloat16(v.w);
            l0.x = __float2bfloat16(v.x - __bfloat162float(h0.x));
            l0.y = __float2bfloat16(v.y - __bfloat162float(h0.y));
            l1.x = __float2bfloat16(v.z - __bfloat162float(h1.x));
            l1.y = __float2bfloat16(v.w - __bfloat162float(h1.y));
            *(__nv_bfloat162*)&hi[i]     = h0;
            *(__nv_bfloat162*)&hi[i + 2] = h1;
            *(__nv_bfloat162*)&lo[i]     = l0;
            *(__nv_bfloat162*)&lo[i + 2] = l1;
        }
    }
}

__global__ void norm_kernel(const float* __restrict__ s_qk_ptr) {
    int i = blockIdx.x * 256 + threadIdx.x;
    if (i >= BNHL) return;
    float s = *s_qk_ptr;
    int b = i >> 15, l = i & 2047;
    int bl = (b << 11) + l;
    g_rq[i] = s * rsqrtf(fmaxf(g_ssqq[i], 1e-24f));
    g_rk[i] = rsqrtf(fmaxf(g_ssqkc[i] + g_ssqkr[bl], 1e-24f));
}

// ---------------- mma.sync bf16 split-3 GEMM (4-stage, tiled grid) ----------------
#define MMS_A_H 0
#define MMS_A_L 16384
#define MMS_B_H 32768
#define MMS_B_L 40960
#define MMS_STAGE 49152
#define MM_SMEM (4 * MMS_STAGE)   // 196608

__device__ __forceinline__ void mm_load_stage(
    uint32_t sbase,
    const __nv_bfloat16* __restrict__ Ah, const __nv_bfloat16* __restrict__ Al, int Astride,
    const __nv_bfloat16* __restrict__ Bh, const __nv_bfloat16* __restrict__ Bl,
    int m0, int n0, int k0, int Kd, int tid)
{
#pragma unroll
    for (int t = 0; t < 4; ++t) {
        int idx = tid + t * 256;
        int row = idx >> 2, c = idx & 3;
        uint32_t so = (uint32_t)(row * 64 + ((c ^ (row & 3)) << 4));
        size_t g = (size_t)(m0 + row) * Astride + k0 + c * 8;
        cpa16(sbase + MMS_A_H + so, Ah + g);
        cpa16(sbase + MMS_A_L + so, Al + g);
    }
#pragma unroll
    for (int t = 0; t < 2; ++t) {
        int idx = tid + t * 256;
        int row = idx >> 2, c = idx & 3;
        uint32_t so = (uint32_t)(row * 64 + ((c ^ (row & 3)) << 4));
        size_t g = (size_t)(n0 + row) * Kd + k0 + c * 8;
        cpa16(sbase + MMS_B_H + so, Bh + g);
        cpa16(sbase + MMS_B_L + so, Bl + g);
    }
}

__global__ void __launch_bounds__(256, 1)
mm_mma_kernel(const __nv_bfloat16* __restrict__ Ahg, const __nv_bfloat16* __restrict__ Alg,
              const __nv_bfloat16* __restrict__ Ahg2, const __nv_bfloat16* __restrict__ Alg2,
              int aswitch, int Astride,
              const __nv_bfloat16* __restrict__ Bhg, const __nv_bfloat16* __restrict__ Blg,
              float* __restrict__ Cf,
              int Nd, int Kd, int epmode) {
    extern __shared__ __align__(1024) char smem[];
    const uint32_t sb = smem_u32(smem);
    const int tid = threadIdx.x, wid = tid >> 5, lane = tid & 31;
    const int m0 = blockIdx.y * 256, n0 = blockIdx.x * 128;
    const int mw = (wid & 3) * 64;
    const int nw = (wid >> 2) * 64;

    const __nv_bfloat16* Auh = (n0 >= aswitch) ? Ahg2 : Ahg;
    const __nv_bfloat16* Aul = (n0 >= aswitch) ? Alg2 : Alg;

    float acc[4][8][4];
#pragma unroll
    for (int i = 0; i < 4; ++i)
#pragma unroll
        for (int j = 0; j < 8; ++j)
#pragma unroll
            for (int q = 0; q < 4; ++q) acc[i][j][q] = 0.f;

    const int nk = Kd >> 5;
#pragma unroll
    for (int s = 0; s < 3; ++s) {
        mm_load_stage(sb + s * MMS_STAGE, Auh, Aul, Astride, Bhg, Blg, m0, n0, s << 5, Kd, tid);
        cp_commit();
    }

    const int jA = lane >> 3, rA = lane & 7;

    int sidx = 0;
    for (int it = 0; it < nk; ++it) {
        cp_wait_group<2>();
        __syncthreads();

        if (it + 3 < nk) {
            int ps = sidx + 3; if (ps >= 4) ps -= 4;
            mm_load_stage(sb + ps * MMS_STAGE, Auh, Aul, Astride, Bhg, Blg,
                          m0, n0, (it + 3) << 5, Kd, tid);
        }
        cp_commit();

        const uint32_t stg = sb + sidx * MMS_STAGE;

#pragma unroll
        for (int ks = 0; ks < 2; ++ks) {
            uint32_t ah[4][4], al[4][4];
#pragma unroll
            for (int i = 0; i < 4; ++i) {
                int m = mw + i * 16 + ((jA & 1) << 3) + rA;
                int c = (ks << 1) + (jA >> 1);
                uint32_t off = (uint32_t)(m * 64 + ((c ^ (m & 3)) << 4));
                ldm_x4(ah[i], stg + MMS_A_H + off);
                ldm_x4(al[i], stg + MMS_A_L + off);
            }
            uint32_t bh[8][2], bl[8][2];
#pragma unroll
            for (int p = 0; p < 4; ++p) {
                int n = nw + p * 16 + ((jA >> 1) << 3) + rA;
                int c = (ks << 1) + (jA & 1);
                uint32_t off = (uint32_t)(n * 64 + ((c ^ (n & 3)) << 4));
                uint32_t tmp[4];
                ldm_x4(tmp, stg + MMS_B_H + off);
                bh[2 * p][0] = tmp[0]; bh[2 * p][1] = tmp[1];
                bh[2 * p + 1][0] = tmp[2]; bh[2 * p + 1][1] = tmp[3];
                ldm_x4(tmp, stg + MMS_B_L + off);
                bl[2 * p][0] = tmp[0]; bl[2 * p][1] = tmp[1];
                bl[2 * p + 1][0] = tmp[2]; bl[2 * p + 1][1] = tmp[3];
            }
#pragma unroll
            for (int i = 0; i < 4; ++i)
#pragma unroll
                for (int j = 0; j < 8; ++j) {
                    mma_bf16(acc[i][j], ah[i], bh[j]);
                    mma_bf16(acc[i][j], al[i], bh[j]);
                    mma_bf16(acc[i][j], ah[i], bl[j]);
                }
        }
        if (++sidx == 4) sidx = 0;
    }

    // ================= epilogues =================
    if (epmode == 0) {
#pragma unroll
        for (int i = 0; i < 4; ++i) {
            int row = m0 + mw + i * 16 + (lane >> 2);
#pragma unroll
            for (int j = 0; j < 8; ++j) {
                int col = n0 + nw + j * 8 + ((lane & 3) << 1);
                *(float2*)&Cf[(size_t)row * Nd + col]       = make_float2(acc[i][j][0], acc[i][j][1]);
                *(float2*)&Cf[(size_t)(row + 8) * Nd + col] = make_float2(acc[i][j][2], acc[i][j][3]);
            }
        }
    } else if (epmode == 1) {
        if (n0 < 2048) {
#pragma unroll
            for (int i = 0; i < 4; ++i) {
                int row = m0 + mw + i * 16 + (lane >> 2);
#pragma unroll
                for (int j = 0; j < 8; ++j) {
                    int col = n0 + nw + j * 8 + ((lane & 3) << 1);
                    store_pair_hl(g_ckvqh, g_ckvql, (size_t)row * 2048 + col, acc[i][j][0], acc[i][j][1]);
                    store_pair_hl(g_ckvqh, g_ckvql, (size_t)(row + 8) * 2048 + col, acc[i][j][2], acc[i][j][3]);
                }
            }
        } else if (nw == 0) {
            // rope-K: cols 2048..2111 -> dr 0..63
#pragma unroll
            for (int i = 0; i < 4; ++i) {
                int rbase = m0 + mw + i * 16 + (lane >> 2);
#pragma unroll
                for (int hh = 0; hh < 2; ++hh) {
                    int rr = rbase + hh * 8;
                    int l = rr & 2047;
                    float ssq = 0.f;
                    float o0[8], o1[8];
#pragma unroll
                    for (int j = 0; j < 8; ++j) {
                        float x1a = acc[i][j][2 * hh], x1b = acc[i][j][2 * hh + 1];
                        int jp = j ^ 4;
                        float sgn = (j < 4) ? -1.f : 1.f;
                        float x2a = acc[i][jp][2 * hh], x2b = acc[i][jp][2 * hh + 1];
                        int i0 = ((j & 3) << 3) + ((lane & 3) << 1);
                        float2 cs0 = g_ropetab[(l << 5) + i0];
                        float2 cs1 = g_ropetab[(l << 5) + i0 + 1];
                        o0[j] = x1a * cs0.x + sgn * x2a * cs0.y;
                        o1[j] = x1b * cs1.x + sgn * x2b * cs1.y;
                        ssq += x1a * x1a + x1b * x1b;
                    }
                    ssq += __shfl_xor_sync(0xffffffffu, ssq, 1);
                    ssq += __shfl_xor_sync(0xffffffffu, ssq, 2);
                    if ((lane & 3) == 0) atomicAdd(&g_ssqkr[rr], ssq);
#pragma unroll
                    for (int j = 0; j < 8; ++j) {
                        int dr = (j << 3) + ((lane & 3) << 1);
                        store_pair_hl(g_krh, g_krl, (size_t)rr * 64 + dr, o0[j], o1[j]);
                    }
                }
            }
        }
    } else {
        int region = n0 >> 11;        // 0 UK, 1 UV, 2 UQ, 3 QR
        if (region < 3) {
            int cbase = (n0 + nw) & 2047;
            int h = cbase >> 7, dbase = cbase & 127;
#pragma unroll
            for (int i = 0; i < 4; ++i) {
                int rbase = m0 + mw + i * 16 + (lane >> 2);
#pragma unroll
                for (int hh = 0; hh < 2; ++hh) {
                    int rr = rbase + hh * 8;
                    int bb = rr >> 11, l = rr & 2047;
                    size_t hidx = (size_t)(bb * NHs + h) * 2048 + l;
                    size_t hb = hidx * 128 + dbase;
                    float ssq = 0.f;
#pragma unroll
                    for (int j = 0; j < 8; ++j) {
                        float v0 = acc[i][j][2 * hh], v1 = acc[i][j][2 * hh + 1];
                        int d = (j << 3) + ((lane & 3) << 1);
                        if (region == 0)      store_pair_hl(g_Kch, g_Kcl, hb + d, v0, v1);
                        else if (region == 1) store_pair_hl(g_Vh,  g_Vl,  hb + d, v0, v1);
                        else                  store_pair_hl(g_Qch, g_Qcl, hb + d, v0, v1);
                        ssq += v0 * v0 + v1 * v1;
                    }
                    if (region != 1) {
                        ssq += __shfl_xor_sync(0xffffffffu, ssq, 1);
                        ssq += __shfl_xor_sync(0xffffffffu, ssq, 2);
                        if ((lane & 3) == 0)
                            atomicAdd(region == 0 ? &g_ssqkc[hidx] : &g_ssqq[hidx], ssq);
                    }
                }
            }
        } else {
            int local0 = (n0 - 6144) + nw;
            int h = local0 >> 6;
#pragma unroll
            for (int i = 0; i < 4; ++i) {
                int rbase = m0 + mw + i * 16 + (lane >> 2);
#pragma unroll
                for (int hh = 0; hh < 2; ++hh) {
                    int rr = rbase + hh * 8;
                    int bb = rr >> 11, l = rr & 2047;
                    size_t hidx = (size_t)(bb * NHs + h) * 2048 + l;
                    float ssq = 0.f;
                    float o0[8], o1[8];
#pragma unroll
                    for (int j = 0; j < 8; ++j) {
                        float x1a = acc[i][j][2 * hh], x1b = acc[i][j][2 * hh + 1];
                        int jp = j ^ 4;
                        float sgn = (j < 4) ? -1.f : 1.f;
                        float x2a = acc[i][jp][2 * hh], x2b = acc[i][jp][2 * hh + 1];
                        int i0 = ((j & 3) << 3) + ((lane & 3) << 1);
                        float2 cs0 = g_ropetab[(l << 5) + i0];
                        float2 cs1 = g_ropetab[(l << 5) + i0 + 1];
                        o0[j] = x1a * cs0.x + sgn * x2a * cs0.y;
                        o1[j] = x1b * cs1.x + sgn * x2b * cs1.y;
                        ssq += x1a * x1a + x1b * x1b;
                    }
                    ssq += __shfl_xor_sync(0xffffffffu, ssq, 1);
                    ssq += __shfl_xor_sync(0xffffffffu, ssq, 2);
                    if ((lane & 3) == 0) atomicAdd(&g_ssqq[hidx], ssq);
#pragma unroll
                    for (int j = 0; j < 8; ++j) {
                        int dr = (j << 3) + ((lane & 3) << 1);
                        store_pair_hl(g_Qrh, g_Qrl, hidx * 64 + dr, o0[j], o1[j]);
                    }
                }
            }
        }
    }
}

// ---------------- tensor-core causal flash attention ----------------
// Fixed-shift softmax: scores are s_qk * cosine <= s_qk (nGPT normalization),
// so exp(s - s_qk) <= 1 always; online max tracking is unnecessary.
#define FQ 128
#define FK 64
#define SQH 0
#define SQL (SQH + FQ*384)
#define SKH (SQL + FQ*384)
#define SKL (SKH + FK*384)
#define SV0H (SKL + FK*384)
#define SV0L (SV0H + FK*256)
#define SV1H (SV0L + FK*256)
#define SV1L (SV1H + FK*256)
#define FLASH_SMEM (SV1L + FK*256)   // 212992

__device__ __forceinline__ void fl_load_q(uint32_t sb, int b, int h, int q0, int tid) {
    size_t cb = (size_t)(b * NHs + h) * Lsz + q0;
    for (int idx = tid; idx < FQ * 24; idx += 256) {
        int r = idx / 24, c = idx % 24;
        uint32_t so = (uint32_t)(r * 384 + ((c ^ (r & 7)) << 4));
        if (c < 16) {
            size_t g = (cb + r) * 128 + c * 8;
            cpa16(sb + SQH + so, g_Qch + g);
            cpa16(sb + SQL + so, g_Qcl + g);
        } else {
            size_t g = (cb + r) * 64 + (c - 16) * 8;
            cpa16(sb + SQH + so, g_Qrh + g);
            cpa16(sb + SQL + so, g_Qrl + g);
        }
    }
}
__device__ __forceinline__ void fl_load_k(uint32_t sb, int b, int h, int k0, int tid) {
    size_t cb = (size_t)(b * NHs + h) * Lsz + k0;
    size_t rb = (size_t)b * Lsz + k0;
    for (int idx = tid; idx < FK * 24; idx += 256) {
        int r = idx / 24, c = idx % 24;
        uint32_t so = (uint32_t)(r * 384 + ((c ^ (r & 7)) << 4));
        if (c < 16) {
            size_t g = (cb + r) * 128 + c * 8;
            cpa16(sb + SKH + so, g_Kch + g);
            cpa16(sb + SKL + so, g_Kcl + g);
        } else {
            size_t g = (rb + r) * 64 + (c - 16) * 8;
            cpa16(sb + SKH + so, g_krh + g);
            cpa16(sb + SKL + so, g_krl + g);
        }
    }
}
__device__ __forceinline__ void fl_load_v(uint32_t sb, uint32_t vH, uint32_t vL,
                                          int b, int h, int k0, int tid) {
    size_t gb = ((size_t)(b * NHs + h) * Lsz + k0) * DHs;
    for (int idx = tid; idx < FK * 16; idx += 256) {
        int r = idx >> 4, c = idx & 15;
        uint32_t so = (uint32_t)(r * 256 + ((c ^ (r & 7)) << 4));
        size_t g = gb + (size_t)r * DHs + c * 8;
        cpa16(sb + vH + so, g_Vh + g);
        cpa16(sb + vL + so, g_Vl + g);
    }
}

__global__ void __launch_bounds__(256, 1)
flashmma_kernel(const float* __restrict__ s_qk_ptr) {
    extern __shared__ __align__(1024) char sm[];
    const uint32_t sb = smem_u32(sm);
    const int tid = threadIdx.x, w = tid >> 5, lane = tid & 31;
    const int qt = (int)(gridDim.x - 1u - blockIdx.x);
    const int h = blockIdx.y, b = blockIdx.z;
    const int q0 = qt * FQ;
    const int mw = w * 16;
    const int jA = lane >> 3, rA = lane & 7;
    const float smax = *s_qk_ptr;           // upper bound on all scores

    fl_load_q(sb, b, h, q0, tid);
    cp_commit();
    fl_load_k(sb, b, h, 0, tid);
    fl_load_v(sb, SV0H, SV0L, b, h, 0, tid);
    cp_commit();

    float oacc[16][4];
#pragma unroll
    for (int j = 0; j < 16; ++j)
#pragma unroll
        for (int q = 0; q < 4; ++q) oacc[j][q] = 0.f;
    float l0 = 0.f, l1 = 0.f;

    const int nkt = 2 * qt + 2;
    const int r0loc = mw + (lane >> 2);
    const int gr0 = q0 + r0loc;

    const float* rqb = g_rq + (size_t)(b * NHs + h) * Lsz;
    const float* rkb = g_rk + (size_t)(b * NHs + h) * Lsz;
    const float rq0 = rqb[gr0], rq1 = rqb[gr0 + 8];

    for (int kt = 0; kt < nkt; ++kt) {
        const int k0 = kt * FK;
        float2 rkv[8];
#pragma unroll
        for (int j = 0; j < 8; ++j)
            rkv[j] = *(const float2*)&rkb[k0 + j * 8 + ((lane & 3) << 1)];

        cp_wait_group<0>();
        __syncthreads();

        // V(kt+1) issued EARLY (double-buffered; target buffer was consumed in iter kt-1)
        if (kt + 1 < nkt) {
            uint32_t vH = ((kt + 1) & 1) ? SV1H : SV0H;
            uint32_t vL = ((kt + 1) & 1) ? SV1L : SV0L;
            fl_load_v(sb, vH, vL, b, h, (kt + 1) * FK, tid);
        }
        cp_commit();

        // ---- S = Q K^T (split-3, unnormalized) ----
        float sacc[8][4];
#pragma unroll
        for (int j = 0; j < 8; ++j)
#pragma unroll
            for (int q = 0; q < 4; ++q) sacc[j][q] = 0.f;

#pragma unroll
        for (int ks = 0; ks < 12; ++ks) {
            int arow = mw + ((jA & 1) << 3) + rA;
            int achk = ks * 2 + (jA >> 1);
            uint32_t aoff = (uint32_t)(arow * 384 + ((achk ^ (arow & 7)) << 4));
            uint32_t ah[4], al[4];
            ldm_x4(ah, sb + SQH + aoff);
            ldm_x4(al, sb + SQL + aoff);
            uint32_t bh[8][2], bl[8][2];
#pragma unroll
            for (int p = 0; p < 4; ++p) {
                int brow = p * 16 + ((jA >> 1) << 3) + rA;
                int bchk = ks * 2 + (jA & 1);
                uint32_t boff = (uint32_t)(brow * 384 + ((bchk ^ (brow & 7)) << 4));
                uint32_t tmp[4];
                ldm_x4(tmp, sb + SKH + boff);
                bh[2 * p][0] = tmp[0]; bh[2 * p][1] = tmp[1];
                bh[2 * p + 1][0] = tmp[2]; bh[2 * p + 1][1] = tmp[3];
                ldm_x4(tmp, sb + SKL + boff);
                bl[2 * p][0] = tmp[0]; bl[2 * p][1] = tmp[1];
                bl[2 * p + 1][0] = tmp[2]; bl[2 * p + 1][1] = tmp[3];
            }
#pragma unroll
            for (int j = 0; j < 8; ++j) {
                mma_bf16(sacc[j], ah, bh[j]);
                mma_bf16(sacc[j], al, bh[j]);
                mma_bf16(sacc[j], ah, bl[j]);
            }
        }

        // ---- causal mask (last two k-tiles only); applied pre-normalization ----
        if (kt >= 2 * qt) {
#pragma unroll
            for (int j = 0; j < 8; ++j) {
                int col = k0 + j * 8 + ((lane & 3) << 1);
                if (col > gr0)     sacc[j][0] = -1e30f;
                if (col + 1 > gr0) sacc[j][1] = -1e30f;
                if (col > gr0 + 8)     sacc[j][2] = -1e30f;
                if (col + 1 > gr0 + 8) sacc[j][3] = -1e30f;
            }
        }

        // ---- fixed-shift softmax: p = exp(rq*rk*s - smax), no max tracking ----
        uint32_t pfh[4][4], pfl[4][4];
        float rs0 = 0.f, rs1 = 0.f;
#pragma unroll
        for (int j = 0; j < 8; ++j) {
            float p0 = __expf(sacc[j][0] * (rq0 * rkv[j].x) - smax);
            float p1 = __expf(sacc[j][1] * (rq0 * rkv[j].y) - smax);
            float p2 = __expf(sacc[j][2] * (rq1 * rkv[j].x) - smax);
            float p3 = __expf(sacc[j][3] * (rq1 * rkv[j].y) - smax);
            rs0 += p0 + p1; rs1 += p2 + p3;
            __nv_bfloat162 h01, h23;
            h01.x = __float2bfloat16(p0); h01.y = __float2bfloat16(p1);
            h23.x = __float2bfloat16(p2); h23.y = __float2bfloat16(p3);
            int t = j >> 1, s = (j & 1) * 2;
            pfh[t][s + 0] = *(uint32_t*)&h01;
            pfh[t][s + 1] = *(uint32_t*)&h23;
            pfl[t][s + 0] = pack_bf162(p0 - __bfloat162float(h01.x),
                                       p1 - __bfloat162float(h01.y));
            pfl[t][s + 1] = pack_bf162(p2 - __bfloat162float(h23.x),
                                       p3 - __bfloat162float(h23.y));
        }
        l0 += rs0;
        l1 += rs1;

        __syncthreads();                // all warps done reading K(kt)

        if (kt + 1 < nkt)
            fl_load_k(sb, b, h, (kt + 1) * FK, tid);
        cp_commit();

        // ---- O += P V (split-3), V from buffer kt&1, P from registers ----
        const uint32_t vH = (kt & 1) ? SV1H : SV0H;
        const uint32_t vL = (kt & 1) ? SV1L : SV0L;
#pragma unroll
        for (int ks = 0; ks < 4; ++ks) {
            int key = ks * 16 + (lane & 15);
#pragma unroll
            for (int p = 0; p < 8; ++p) {
                int dch = p * 2 + (lane >> 4);
                uint32_t voff = (uint32_t)(key * 256 + ((dch ^ (key & 7)) << 4));
                uint32_t th[4], tl[4];
                ldm_x4_t(th, sb + vH + voff);
                ldm_x4_t(tl, sb + vL + voff);
                mma_bf16(oacc[2 * p], pfh[ks], th);
                mma_bf16(oacc[2 * p], pfl[ks], th);
                mma_bf16(oacc[2 * p], pfh[ks], tl);
                mma_bf16(oacc[2 * p + 1], pfh[ks], th + 2);
                mma_bf16(oacc[2 * p + 1], pfl[ks], th + 2);
                mma_bf16(oacc[2 * p + 1], pfh[ks], tl + 2);
            }
        }
    }

    // ---- sum quad partial l (each lane holds partial over its 2-col pairs) ----
#pragma unroll
    for (int o = 1; o <= 2; o <<= 1) {
        l0 += __shfl_xor_sync(0xffffffffu, l0, o);
        l1 += __shfl_xor_sync(0xffffffffu, l1, o);
    }

    // ---- epilogue: normalize, split, write (B,L,D) bf16 hi/lo ----
    float inv0 = 1.0f / l0, inv1 = 1.0f / l1;
    size_t ob0 = ((size_t)(b * Lsz + gr0)) * Dsz + h * DHs;
    size_t ob1 = ((size_t)(b * Lsz + gr0 + 8)) * Dsz + h * DHs;
#pragma unroll
    for (int j = 0; j < 16; ++j) {
        int d = j * 8 + ((lane & 3) << 1);
        store_pair_hl(g_aoh, g_aol, ob0 + d, oacc[j][0] * inv0, oacc[j][1] * inv0);
        store_pair_hl(g_aoh, g_aol, ob1 + d, oacc[j][2] * inv1, oacc[j][3] * inv1);
    }
}

// ---------------- launcher ----------------
extern "C" void kernel_launch(void* const* d_in, const int* in_sizes, int n_in,
                              void* d_out, int out_size) {
    const float* x     = (const float*)d_in[0];
    const float* W_DKV = (const float*)d_in[1];
    const float* W_UK  = (const float*)d_in[2];
    const float* W_UV  = (const float*)d_in[3];
    const float* W_DQ  = (const float*)d_in[4];
    const float* W_UQ  = (const float*)d_in[5];
    const float* W_QR  = (const float*)d_in[6];
    const float* W_KR  = (const float*)d_in[7];
    const float* W_O   = (const float*)d_in[8];
    const float* s_qk  = (const float*)d_in[9];
    float* out = (float*)d_out;

    __nv_bfloat16 *xh, *xl, *cvh, *cvl, *aoh, *aol;
    __nv_bfloat16 *wdh, *wdl, *wuh, *wul, *woh, *wol;
    cudaGetSymbolAddress((void**)&xh, g_xh);     cudaGetSymbolAddress((void**)&xl, g_xl);
    cudaGetSymbolAddress((void**)&cvh, g_ckvqh); cudaGetSymbolAddress((void**)&cvl, g_ckvql);
    cudaGetSymbolAddress((void**)&aoh, g_aoh);   cudaGetSymbolAddress((void**)&aol, g_aol);
    cudaGetSymbolAddress((void**)&wdh, g_wdh);   cudaGetSymbolAddress((void**)&wdl, g_wdl);
    cudaGetSymbolAddress((void**)&wuh, g_wuh);   cudaGetSymbolAddress((void**)&wul, g_wul);
    cudaGetSymbolAddress((void**)&woh, g_woh);   cudaGetSymbolAddress((void**)&wol, g_wol);

    cudaFuncSetAttribute(mm_mma_kernel, cudaFuncAttributeMaxDynamicSharedMemorySize, MM_SMEM);
    cudaFuncSetAttribute(flashmma_kernel, cudaFuncAttributeMaxDynamicSharedMemorySize, FLASH_SMEM);

    // fused prep: weight transpose-splits + rope table + ssq zero
    prep_kernel<<<PB_TOTAL, 256>>>(W_DKV, W_DQ, W_KR, W_UK, W_UV, W_UQ, W_QR, W_O);

    // split x
    { int n = Msz * Dsz; split_kernel<<<(n / 8 + 255) / 256, 256>>>(x, xh, xl, n); }

    // fused down-projection: N=2176 -> bf16 ckvq + rope-K compact
    mm_mma_kernel<<<dim3(2176/128, Msz/256), 256, MM_SMEM>>>(
        xh, xl, xh, xl, 1 << 30, Dsz,
        wdh, wdl, nullptr, 2176, Dsz, /*epmode=*/1);

    // fused up-projection: N=7168 -> Kc, V, Qc, rope-Q (attention layout, bf16 hi/lo)
    mm_mma_kernel<<<dim3(7168/128, Msz/256), 256, MM_SMEM>>>(
        cvh, cvl, cvh + 1024, cvl + 1024, 4096, 2048,
        wuh, wul, nullptr, 7168, DCs, /*epmode=*/2);

    // norms
    norm_kernel<<<BNHL / 256, 256>>>(s_qk);

    // tensor-core causal flash attention -> aoh/aol
    flashmma_kernel<<<dim3(Lsz / FQ, NHs, Bsz), 256, FLASH_SMEM>>>(s_qk);

    // output projection
    mm_mma_kernel<<<dim3(Dsz/128, Msz/256), 256, MM_SMEM>>>(
        aoh, aol, aoh, aol, 1 << 30, Dsz,
        woh, wol, out, Dsz, Dsz, /*epmode=*/0);
}